// round 6
// baseline (speedup 1.0000x reference)
#include <cuda_runtime.h>
#include <cuda_bf16.h>
#include <cstdint>

#define B_    32
#define NTOK  3136
#define NH    12
#define D_    32

// ---------------- scratch (device globals; no allocation allowed) -------------
__device__ __align__(16) float g_Q[(size_t)B_ * NH * NTOK * D_];   // [b*12+h][n][d]
__device__ __align__(16) float g_K[(size_t)B_ * NH * NTOK * D_];
__device__ __align__(16) float g_V[(size_t)B_ * NH * NTOK * D_];
__device__ __align__(16) float g_Q1[B_ * 4 * 784 * D_];
__device__ __align__(16) float g_K1[B_ * 4 * 784 * D_];
__device__ __align__(16) float g_V1[B_ * 4 * 784 * D_];
__device__ __align__(16) float g_Q2[B_ * 4 * 196 * D_];
__device__ __align__(16) float g_K2[B_ * 4 * 196 * D_];
__device__ __align__(16) float g_V2[B_ * 4 * 196 * D_];

#define XELEMS ((size_t)B_ * NTOK * 384)
__device__ __align__(16) __nv_bfloat16 g_Xh[XELEMS];
__device__ __align__(16) __nv_bfloat16 g_Xl[XELEMS];
__device__ __align__(16) __nv_bfloat16 g_Zh[XELEMS];
__device__ __align__(16) __nv_bfloat16 g_Zl[XELEMS];
// transposed weights, [n][k]: rows 0..1151 = qkv output cols, 1152..1535 = proj cols
__device__ __align__(16) __nv_bfloat16 g_WTh[1536 * 384];
__device__ __align__(16) __nv_bfloat16 g_WTl[1536 * 384];

// ---------------- helpers -------------------------------------------------------
__device__ __forceinline__ uint32_t smem_u32(const void* p) {
    uint32_t a;
    asm("{ .reg .u64 t; cvta.to.shared.u64 t, %1; cvt.u32.u64 %0, t; }" : "=r"(a) : "l"(p));
    return a;
}
__device__ __forceinline__ void cp16(uint32_t dst, const void* src) {
    asm volatile("cp.async.cg.shared.global [%0], [%1], 16;" :: "r"(dst), "l"(src));
}
__device__ __forceinline__ void ldm_x4(uint32_t* r, uint32_t a) {
    asm volatile("ldmatrix.sync.aligned.m8n8.x4.shared.b16 {%0,%1,%2,%3}, [%4];"
                 : "=r"(r[0]), "=r"(r[1]), "=r"(r[2]), "=r"(r[3]) : "r"(a));
}
__device__ __forceinline__ void mma16816(float* d, const uint32_t* a, const uint32_t* b) {
    asm volatile(
        "mma.sync.aligned.m16n8k16.row.col.f32.bf16.bf16.f32 "
        "{%0,%1,%2,%3}, {%4,%5,%6,%7}, {%8,%9}, {%0,%1,%2,%3};"
        : "+f"(d[0]), "+f"(d[1]), "+f"(d[2]), "+f"(d[3])
        : "r"(a[0]), "r"(a[1]), "r"(a[2]), "r"(a[3]), "r"(b[0]), "r"(b[1]));
}

// ---------------- split / transpose kernels ------------------------------------
__global__ void split_x(const float4* __restrict__ src) {
    uint2* hiP = (uint2*)g_Xh;
    uint2* loP = (uint2*)g_Xl;
    const int n4 = (int)(XELEMS / 4);
    const int stride = gridDim.x * blockDim.x;
    for (int i = blockIdx.x * blockDim.x + threadIdx.x; i < n4; i += stride) {
        float4 f = src[i];
        uint32_t x = __float_as_uint(f.x), y = __float_as_uint(f.y);
        uint32_t z = __float_as_uint(f.z), w = __float_as_uint(f.w);
        uint2 h;
        h.x = __byte_perm(x, y, 0x7632);
        h.y = __byte_perm(z, w, 0x7632);
        float l0 = f.x - __uint_as_float(x & 0xFFFF0000u);
        float l1 = f.y - __uint_as_float(y & 0xFFFF0000u);
        float l2 = f.z - __uint_as_float(z & 0xFFFF0000u);
        float l3 = f.w - __uint_as_float(w & 0xFFFF0000u);
        uint2 l;
        asm("cvt.rn.bf16x2.f32 %0, %1, %2;" : "=r"(l.x) : "f"(l1), "f"(l0));
        asm("cvt.rn.bf16x2.f32 %0, %1, %2;" : "=r"(l.y) : "f"(l3), "f"(l2));
        hiP[i] = h;
        loP[i] = l;
    }
}

__global__ void make_wt_qkv(const float* __restrict__ Wq, const float* __restrict__ Wkv) {
    int idx = blockIdx.x * 256 + threadIdx.x;
    if (idx >= 1152 * 384) return;
    int nrow = idx / 384, k = idx % 384;
    float v = (nrow < 384) ? Wq[(size_t)k * 384 + nrow]
                           : Wkv[(size_t)k * 768 + (nrow - 384)];
    uint32_t bits = __float_as_uint(v);
    float hf = __uint_as_float(bits & 0xFFFF0000u);
    g_WTh[idx] = __ushort_as_bfloat16((unsigned short)(bits >> 16));
    g_WTl[idx] = __float2bfloat16(v - hf);
}
__global__ void make_wt_proj(const float* __restrict__ Wproj) {
    int idx = blockIdx.x * 256 + threadIdx.x;
    if (idx >= 384 * 384) return;
    int nrow = idx / 384, k = idx % 384;
    float v = Wproj[(size_t)k * 384 + nrow];
    uint32_t bits = __float_as_uint(v);
    float hf = __uint_as_float(bits & 0xFFFF0000u);
    g_WTh[1152 * 384 + idx] = __ushort_as_bfloat16((unsigned short)(bits >> 16));
    g_WTl[1152 * 384 + idx] = __float2bfloat16(v - hf);
}

// ---------------- HMMA GEMM: 128x128 tile, 256 thr, chunk K=48, 2 stages --------
// smem row stride 112B (16B aligned; 28r mod 32 distinct -> conflict-free ldmatrix)
#define CHROWB 112
#define BUFB   (128 * CHROWB)        // 14336 bytes per operand buffer
#define STAGEB (4 * BUFB)            // 57344 (Ah, Al, Bh, Bl)
#define SMEM_GEMM (2 * STAGEB)       // 114688
#define NCHUNK 8                     // 384 / 48

__global__ __launch_bounds__(256, 2)
void gemm_mma(const float* __restrict__ bias, float* __restrict__ out, int mode)
{
    extern __shared__ __align__(16) char smem[];
    const uint32_t sb = smem_u32(smem);
    const int tid = threadIdx.x, lane = tid & 31, wid = tid >> 5;
    const int warpM = wid & 1, warpN = wid >> 1;     // 2 x 4 warp grid
    const int rowBase = blockIdx.y * 128, colBase = blockIdx.x * 128;

    const __nv_bfloat16* Ahg = (mode == 0 ? g_Xh : g_Zh) + (size_t)rowBase * 384;
    const __nv_bfloat16* Alg = (mode == 0 ? g_Xl : g_Zl) + (size_t)rowBase * 384;
    const int brow = (mode == 0 ? 0 : 1152) + colBase;
    const __nv_bfloat16* Bhg = g_WTh + (size_t)brow * 384;
    const __nv_bfloat16* Blg = g_WTl + (size_t)brow * 384;

    // loader: 256 threads; thread -> row (tid>>1), half (tid&1) covering 3 of 6 16B segs
    const int lr = tid >> 1, lh = tid & 1;
    const uint32_t lso = (uint32_t)(lr * CHROWB + lh * 48);

    float acc[4][4][4];
#pragma unroll
    for (int i = 0; i < 4; i++)
#pragma unroll
        for (int j = 0; j < 4; j++)
#pragma unroll
            for (int q = 0; q < 4; q++) acc[i][j][q] = 0.f;

    auto load_chunk = [&](int c, int stg) {
        const uint32_t base = sb + stg * STAGEB + lso;
        const size_t go = (size_t)lr * 384 + c * 48 + lh * 24;
#pragma unroll
        for (int j = 0; j < 3; j++) {
            cp16(base + j * 16,            Ahg + go + j * 8);
            cp16(base + BUFB + j * 16,     Alg + go + j * 8);
            cp16(base + 2 * BUFB + j * 16, Bhg + go + j * 8);
            cp16(base + 3 * BUFB + j * 16, Blg + go + j * 8);
        }
        asm volatile("cp.async.commit_group;" ::: "memory");
    };

    // ldmatrix per-lane addressing
    const int rA = lane & 15;
    const uint32_t cA16 = (lane & 16) ? 16u : 0u;
    const int rB = (lane & 7) + ((lane & 16) ? 8 : 0);
    const uint32_t cB16 = (lane & 8) ? 16u : 0u;

    load_chunk(0, 0);
    load_chunk(1, 1);

    for (int c = 0; c < NCHUNK; c++) {
        if (c < NCHUNK - 1) asm volatile("cp.async.wait_group 1;" ::: "memory");
        else                asm volatile("cp.async.wait_group 0;" ::: "memory");
        __syncthreads();

        const uint32_t base = sb + (c & 1) * STAGEB;
#pragma unroll
        for (int kk = 0; kk < 48; kk += 16) {
            uint32_t ah[4][4], al[4][4], bx[4][2];
            // ---- LDSM ah + bh, then hh MMAs (al/bl loads hidden under MMA exec)
#pragma unroll
            for (int i = 0; i < 4; i++) {
                uint32_t addr = base +
                    (uint32_t)((warpM * 64 + i * 16 + rA) * CHROWB) + (uint32_t)(kk * 2) + cA16;
                ldm_x4(ah[i], addr);
            }
#pragma unroll
            for (int jj = 0; jj < 2; jj++) {
                uint32_t rr[4];
                uint32_t addr = base + 2 * BUFB +
                    (uint32_t)((warpN * 32 + jj * 16 + rB) * CHROWB) + (uint32_t)(kk * 2) + cB16;
                ldm_x4(rr, addr);
                bx[2 * jj][0] = rr[0]; bx[2 * jj][1] = rr[1];
                bx[2 * jj + 1][0] = rr[2]; bx[2 * jj + 1][1] = rr[3];
            }
#pragma unroll
            for (int i = 0; i < 4; i++)
#pragma unroll
                for (int j = 0; j < 4; j++) mma16816(acc[i][j], ah[i], bx[j]);
            // ---- LDSM al under hh execution, then lh MMAs
#pragma unroll
            for (int i = 0; i < 4; i++) {
                uint32_t addr = base + BUFB +
                    (uint32_t)((warpM * 64 + i * 16 + rA) * CHROWB) + (uint32_t)(kk * 2) + cA16;
                ldm_x4(al[i], addr);
            }
#pragma unroll
            for (int i = 0; i < 4; i++)
#pragma unroll
                for (int j = 0; j < 4; j++) mma16816(acc[i][j], al[i], bx[j]);
            // ---- LDSM bl under lh execution, then hl MMAs
#pragma unroll
            for (int jj = 0; jj < 2; jj++) {
                uint32_t rr[4];
                uint32_t addr = base + 3 * BUFB +
                    (uint32_t)((warpN * 32 + jj * 16 + rB) * CHROWB) + (uint32_t)(kk * 2) + cB16;
                ldm_x4(rr, addr);
                bx[2 * jj][0] = rr[0]; bx[2 * jj][1] = rr[1];
                bx[2 * jj + 1][0] = rr[2]; bx[2 * jj + 1][1] = rr[3];
            }
#pragma unroll
            for (int i = 0; i < 4; i++)
#pragma unroll
                for (int j = 0; j < 4; j++) mma16816(acc[i][j], ah[i], bx[j]);
        }
        __syncthreads();
        if (c + 2 < NCHUNK) load_chunk(c + 2, c & 1);
    }

    // ---------------- epilogue ----------------
#pragma unroll
    for (int j = 0; j < 4; j++) {
        const int cg = colBase + warpN * 32 + j * 8 + 2 * (lane & 3);
#pragma unroll
        for (int i = 0; i < 4; i++) {
            const int m = rowBase + warpM * 64 + i * 16 + (lane >> 2);
            if (mode == 0) {
                int bb = m / NTOK, n = m % NTOK;
                float* dst;
                int d;
                if (cg < 384) {
                    dst = g_Q + (((size_t)bb * 12 + (cg >> 5)) * NTOK + n) * 32;
                    d = cg & 31;
                } else {
                    int j2 = cg - 384;
                    float* basep = (j2 >= 384) ? g_V : g_K;
                    dst = basep + (((size_t)bb * 12 + ((j2 >> 5) % 12)) * NTOK + n) * 32;
                    d = j2 & 31;
                }
                *(float2*)(dst + d)          = make_float2(acc[i][j][0], acc[i][j][1]);
                *(float2*)(dst + d + 8 * 32) = make_float2(acc[i][j][2], acc[i][j][3]);
            } else {
                float b0 = bias[cg], b1 = bias[cg + 1];
                *(float2*)(out + (size_t)m * 384 + cg) =
                    make_float2(acc[i][j][0] + b0, acc[i][j][1] + b1);
                *(float2*)(out + (size_t)(m + 8) * 384 + cg) =
                    make_float2(acc[i][j][2] + b0, acc[i][j][3] + b1);
            }
        }
    }
}

// ---------------- fused depthwise convs ------------------------------------------
__global__ void dwconv_fused(const float* __restrict__ w1, const float* __restrict__ b1,
                             const float* __restrict__ w2, const float* __restrict__ b2)
{
    int which = blockIdx.y % 3;          // 0=Q 1=K 2=V
    int op    = blockIdx.y / 3;          // 0=conv1 1=conv2
    const float* src = which == 0 ? g_Q : which == 1 ? g_K : g_V;
    int bg = blockIdx.x;
    int b = bg >> 2, hl = bg & 3;

    if (op == 0) {
        float* dst = which == 0 ? g_Q1 : which == 1 ? g_K1 : g_V1;
        const float* s = src + ((size_t)(b * 12 + 4 + hl)) * NTOK * 32;
        float* d = dst + (size_t)bg * 784 * 32;
        for (int idx = threadIdx.x; idx < 784 * 32; idx += blockDim.x) {
            int c = idx & 31;
            int xy = idx >> 5;
            int xo = xy % 28, yo = xy / 28;
            float acc = b1[c];
#pragma unroll
            for (int i = 0; i < 2; i++)
#pragma unroll
                for (int j = 0; j < 2; j++)
                    acc = fmaf(s[((2 * yo + i) * 56 + 2 * xo + j) * 32 + c],
                               w1[(i * 2 + j) * 32 + c], acc);
            d[idx] = acc;
        }
    } else {
        float* dst = which == 0 ? g_Q2 : which == 1 ? g_K2 : g_V2;
        const float* s = src + ((size_t)(b * 12 + 8 + hl)) * NTOK * 32;
        float* d = dst + (size_t)bg * 196 * 32;
        for (int idx = threadIdx.x; idx < 196 * 32; idx += blockDim.x) {
            int c = idx & 31;
            int xy = idx >> 5;
            int xo = xy % 14, yo = xy / 14;
            float acc = b2[c];
#pragma unroll
            for (int i = 0; i < 2; i++) {
                int iy = 4 * yo - 1 + 2 * i;
                if (iy < 0 || iy >= 56) continue;
#pragma unroll
                for (int j = 0; j < 2; j++) {
                    int ix = 4 * xo - 1 + 2 * j;
                    if (ix < 0 || ix >= 56) continue;
                    acc = fmaf(s[(iy * 56 + ix) * 32 + c], w2[(i * 2 + j) * 32 + c], acc);
                }
            }
            d[idx] = acc;
        }
    }
}

// ---------------- windowed attention: reg-cached K, batched PV -------------------
__global__ __launch_bounds__(256)
void window_attn(int scaleId)
{
    __shared__ __align__(16) float sQ[49 * 36];
    __shared__ __align__(16) float sK[64 * 36];
    __shared__ __align__(16) float sV[49 * 36];

    const float *Qb, *Kb, *Vb;
    int side, nside, headOff, ntile, seq;
    if (scaleId == 0)      { Qb = g_Q;  Kb = g_K;  Vb = g_V;  side = 56; nside = 8; headOff = 0; ntile = 1;  seq = 3136; }
    else if (scaleId == 1) { Qb = g_Q1; Kb = g_K1; Vb = g_V1; side = 28; nside = 4; headOff = 4; ntile = 4;  seq = 784;  }
    else                   { Qb = g_Q2; Kb = g_K2; Vb = g_V2; side = 14; nside = 2; headOff = 8; ntile = 16; seq = 196;  }

    const int nwin = nside * nside;
    const int rg = blockIdx.x % nwin;
    const int hl = (blockIdx.x / nwin) & 3;
    const int b  = blockIdx.x / (nwin * 4);
    const int hb = rg / nside, wb = rg % nside;

    const int imgIdx = (scaleId == 0) ? (b * 12 + hl) : (b * 4 + hl);
    const float* Qp = Qb + (size_t)imgIdx * seq * 32;
    const float* Kp = Kb + (size_t)imgIdx * seq * 32;
    const float* Vp = Vb + (size_t)imgIdx * seq * 32;

    for (int idx = threadIdx.x; idx < 49 * 32; idx += 256) {
        int p = idx >> 5, k = idx & 31;
        int yy = hb * 7 + p / 7, xx = wb * 7 + p % 7;
        int off = (yy * side + xx) * 32 + k;
        sQ[p * 36 + k] = Qp[off];
        sK[p * 36 + k] = Kp[off];
        sV[p * 36 + k] = Vp[off];
    }
    for (int idx = threadIdx.x; idx < 15 * 36; idx += 256)
        sK[49 * 36 + idx] = 0.f;
    __syncthreads();

    const int lane = threadIdx.x & 31;
    const int warp = threadIdx.x >> 5;
    const float scale = 0.17677669529663687f;
    const bool hi = (lane < 17);

    float4 kA[8], kB[8];
#pragma unroll
    for (int j = 0; j < 8; j++) {
        kA[j] = *(const float4*)&sK[lane * 36 + 4 * j];
        kB[j] = *(const float4*)&sK[(lane + 32) * 36 + 4 * j];
    }

    float e0v[7], e1v[7], rinv[7], accv[7];
#pragma unroll
    for (int i = 0; i < 7; i++) { e0v[i] = 0.f; e1v[i] = 0.f; rinv[i] = 0.f; accv[i] = 0.f; }

#pragma unroll
    for (int i = 0; i < 7; i++) {
        int p = warp + 8 * i;
        if (p < 49) {
            float s0 = 0.f, s1 = 0.f;
#pragma unroll
            for (int j = 0; j < 8; j++) {
                float4 qv = *(const float4*)&sQ[p * 36 + 4 * j];
                s0 = fmaf(qv.x, kA[j].x, s0); s0 = fmaf(qv.y, kA[j].y, s0);
                s0 = fmaf(qv.z, kA[j].z, s0); s0 = fmaf(qv.w, kA[j].w, s0);
                s1 = fmaf(qv.x, kB[j].x, s1); s1 = fmaf(qv.y, kB[j].y, s1);
                s1 = fmaf(qv.z, kB[j].z, s1); s1 = fmaf(qv.w, kB[j].w, s1);
            }
            float t0 = s0 * scale;
            float t1 = s1 * scale;
            float m = hi ? fmaxf(t0, t1) : t0;
#pragma unroll
            for (int o = 16; o > 0; o >>= 1) m = fmaxf(m, __shfl_xor_sync(0xffffffffu, m, o));
            float e0 = __expf(t0 - m);
            float e1 = hi ? __expf(t1 - m) : 0.f;
            float sum = e0 + e1;
#pragma unroll
            for (int o = 16; o > 0; o >>= 1) sum += __shfl_xor_sync(0xffffffffu, sum, o);
            e0v[i] = e0;
            e1v[i] = e1;
            rinv[i] = 1.f / sum;
        }
    }

    for (int q = 0; q < 49; q++) {
        float v = sV[q * 36 + lane];
        if (q < 32) {
#pragma unroll
            for (int i = 0; i < 7; i++) {
                float pq = __shfl_sync(0xffffffffu, e0v[i], q);
                accv[i] = fmaf(pq, v, accv[i]);
            }
        } else {
#pragma unroll
            for (int i = 0; i < 7; i++) {
                float pq = __shfl_sync(0xffffffffu, e1v[i], q - 32);
                accv[i] = fmaf(pq, v, accv[i]);
            }
        }
    }

#pragma unroll
    for (int i = 0; i < 7; i++) {
        int p = warp + 8 * i;
        if (p < 49) {
            float val = accv[i] * rinv[i];
            __nv_bfloat16 h = __float2bfloat16(val);
            __nv_bfloat16 l = __float2bfloat16(val - __bfloat162float(h));
            int col = (headOff + hl) * 32 + lane;
            for (int t = 0; t < ntile; t++) {
                int nout = (t * nwin + rg) * 49 + p;
                size_t off = ((size_t)b * NTOK + nout) * 384 + col;
                g_Zh[off] = h;
                g_Zl[off] = l;
            }
        }
    }
}

// ---------------- launch ---------------------------------------------------------
extern "C" void kernel_launch(void* const* d_in, const int* in_sizes, int n_in,
                              void* d_out, int out_size)
{
    const float* x     = (const float*)d_in[0];
    const float* Wq    = (const float*)d_in[1];
    const float* Wkv   = (const float*)d_in[2];
    const float* Wproj = (const float*)d_in[3];
    const float* bproj = (const float*)d_in[4];
    const float* c1w   = (const float*)d_in[5];
    const float* c1b   = (const float*)d_in[6];
    const float* c2w   = (const float*)d_in[7];
    const float* c2b   = (const float*)d_in[8];
    float* out = (float*)d_out;

    cudaFuncSetAttribute(gemm_mma, cudaFuncAttributeMaxDynamicSharedMemorySize, SMEM_GEMM);

    split_x<<<4704, 256>>>((const float4*)x);
    make_wt_qkv<<<1728, 256>>>(Wq, Wkv);
    make_wt_proj<<<576, 256>>>(Wproj);
    gemm_mma<<<dim3(9, 784), 256, SMEM_GEMM>>>(nullptr, nullptr, 0);   // 4th launch -> ncu
    dwconv_fused<<<dim3(128, 6), 256>>>(c1w, c1b, c2w, c2b);
    window_attn<<<32 * 4 * 64, 256>>>(0);
    window_attn<<<32 * 4 * 16, 256>>>(1);
    window_attn<<<32 * 4 * 4,  256>>>(2);
    gemm_mma<<<dim3(3, 784), 256, SMEM_GEMM>>>(bproj, out, 1);
}

// round 7
// speedup vs baseline: 1.2667x; 1.2667x over previous
#include <cuda_runtime.h>
#include <cuda_bf16.h>
#include <cstdint>

#define B_    32
#define NTOK  3136
#define NH    12
#define D_    32

// ---------------- scratch (device globals; no allocation allowed) -------------
__device__ __align__(16) float g_Q[(size_t)B_ * NH * NTOK * D_];   // [b*12+h][n][d]
__device__ __align__(16) float g_K[(size_t)B_ * NH * NTOK * D_];
__device__ __align__(16) float g_V[(size_t)B_ * NH * NTOK * D_];
__device__ __align__(16) float g_Q1[B_ * 4 * 784 * D_];
__device__ __align__(16) float g_K1[B_ * 4 * 784 * D_];
__device__ __align__(16) float g_V1[B_ * 4 * 784 * D_];
__device__ __align__(16) float g_Q2[B_ * 4 * 196 * D_];
__device__ __align__(16) float g_K2[B_ * 4 * 196 * D_];
__device__ __align__(16) float g_V2[B_ * 4 * 196 * D_];

#define XELEMS ((size_t)B_ * NTOK * 384)
__device__ __align__(16) __nv_bfloat16 g_Xh[XELEMS];
__device__ __align__(16) __nv_bfloat16 g_Xl[XELEMS];
__device__ __align__(16) __nv_bfloat16 g_Zh[XELEMS];
__device__ __align__(16) __nv_bfloat16 g_Zl[XELEMS];
// transposed weights, [n][k]: rows 0..1151 = qkv output cols, 1152..1535 = proj cols
__device__ __align__(16) __nv_bfloat16 g_WTh[1536 * 384];
__device__ __align__(16) __nv_bfloat16 g_WTl[1536 * 384];

// ---------------- helpers -------------------------------------------------------
__device__ __forceinline__ uint32_t smem_u32(const void* p) {
    uint32_t a;
    asm("{ .reg .u64 t; cvta.to.shared.u64 t, %1; cvt.u32.u64 %0, t; }" : "=r"(a) : "l"(p));
    return a;
}
__device__ __forceinline__ void cp16(uint32_t dst, const void* src) {
    asm volatile("cp.async.cg.shared.global [%0], [%1], 16;" :: "r"(dst), "l"(src));
}
__device__ __forceinline__ void ldm_x4(uint32_t* r, uint32_t a) {
    asm volatile("ldmatrix.sync.aligned.m8n8.x4.shared.b16 {%0,%1,%2,%3}, [%4];"
                 : "=r"(r[0]), "=r"(r[1]), "=r"(r[2]), "=r"(r[3]) : "r"(a));
}
__device__ __forceinline__ void mma16816(float* d, const uint32_t* a, const uint32_t* b) {
    asm volatile(
        "mma.sync.aligned.m16n8k16.row.col.f32.bf16.bf16.f32 "
        "{%0,%1,%2,%3}, {%4,%5,%6,%7}, {%8,%9}, {%0,%1,%2,%3};"
        : "+f"(d[0]), "+f"(d[1]), "+f"(d[2]), "+f"(d[3])
        : "r"(a[0]), "r"(a[1]), "r"(a[2]), "r"(a[3]), "r"(b[0]), "r"(b[1]));
}

// ---------------- split / transpose kernels ------------------------------------
__global__ void split_x(const float4* __restrict__ src) {
    uint2* hiP = (uint2*)g_Xh;
    uint2* loP = (uint2*)g_Xl;
    const int n4 = (int)(XELEMS / 4);
    const int stride = gridDim.x * blockDim.x;
    for (int i = blockIdx.x * blockDim.x + threadIdx.x; i < n4; i += stride) {
        float4 f = src[i];
        uint32_t x = __float_as_uint(f.x), y = __float_as_uint(f.y);
        uint32_t z = __float_as_uint(f.z), w = __float_as_uint(f.w);
        uint2 h;
        h.x = __byte_perm(x, y, 0x7632);
        h.y = __byte_perm(z, w, 0x7632);
        float l0 = f.x - __uint_as_float(x & 0xFFFF0000u);
        float l1 = f.y - __uint_as_float(y & 0xFFFF0000u);
        float l2 = f.z - __uint_as_float(z & 0xFFFF0000u);
        float l3 = f.w - __uint_as_float(w & 0xFFFF0000u);
        uint2 l;
        asm("cvt.rn.bf16x2.f32 %0, %1, %2;" : "=r"(l.x) : "f"(l1), "f"(l0));
        asm("cvt.rn.bf16x2.f32 %0, %1, %2;" : "=r"(l.y) : "f"(l3), "f"(l2));
        hiP[i] = h;
        loP[i] = l;
    }
}

__global__ void make_wt_qkv(const float* __restrict__ Wq, const float* __restrict__ Wkv) {
    int idx = blockIdx.x * 256 + threadIdx.x;
    if (idx >= 1152 * 384) return;
    int nrow = idx / 384, k = idx % 384;
    float v = (nrow < 384) ? Wq[(size_t)k * 384 + nrow]
                           : Wkv[(size_t)k * 768 + (nrow - 384)];
    uint32_t bits = __float_as_uint(v);
    float hf = __uint_as_float(bits & 0xFFFF0000u);
    g_WTh[idx] = __ushort_as_bfloat16((unsigned short)(bits >> 16));
    g_WTl[idx] = __float2bfloat16(v - hf);
}
__global__ void make_wt_proj(const float* __restrict__ Wproj) {
    int idx = blockIdx.x * 256 + threadIdx.x;
    if (idx >= 384 * 384) return;
    int nrow = idx / 384, k = idx % 384;
    float v = Wproj[(size_t)k * 384 + nrow];
    uint32_t bits = __float_as_uint(v);
    float hf = __uint_as_float(bits & 0xFFFF0000u);
    g_WTh[1152 * 384 + idx] = __ushort_as_bfloat16((unsigned short)(bits >> 16));
    g_WTl[1152 * 384 + idx] = __float2bfloat16(v - hf);
}

// ---------------- HMMA GEMM: 128x128 tile, chunk K=32, 2 stages (R3 structure) --
// smem tile: 128 rows x 32 bf16, row stride 40 bf16 (80B) -> conflict-free ldmatrix
#define TSROW 40
#define TILEB (128 * TSROW * 2)      // 10240
#define STAGEB (4 * TILEB)           // 40960 (Ah, Al, Bh, Bl)
#define SMEM_GEMM (2 * STAGEB)       // 81920

__global__ __launch_bounds__(256, 2)
void gemm_mma(const float* __restrict__ bias, float* __restrict__ out, int mode)
{
    extern __shared__ __align__(16) char smem[];
    const uint32_t sb = smem_u32(smem);
    const int tid = threadIdx.x, lane = tid & 31, wid = tid >> 5;
    const int warpM = wid & 1, warpN = wid >> 1;    // 2 x 4 warp grid
    const int rowBase = blockIdx.y * 128, colBase = blockIdx.x * 128;

    const __nv_bfloat16* Ahg = (mode == 0 ? g_Xh : g_Zh) + (size_t)rowBase * 384;
    const __nv_bfloat16* Alg = (mode == 0 ? g_Xl : g_Zl) + (size_t)rowBase * 384;
    const int brow = (mode == 0 ? 0 : 1152) + colBase;
    const __nv_bfloat16* Bhg = g_WTh + (size_t)brow * 384;
    const __nv_bfloat16* Blg = g_WTl + (size_t)brow * 384;

    // per-thread load coords (2 segments per buffer per thread; 512 segs/buffer)
    const int r0 = tid >> 2, s0 = tid & 3;
    const int r1 = (tid + 256) >> 2, s1 = tid & 3;

    float acc[4][4][4];
#pragma unroll
    for (int i = 0; i < 4; i++)
#pragma unroll
        for (int j = 0; j < 4; j++)
#pragma unroll
            for (int q = 0; q < 4; q++) acc[i][j][q] = 0.f;

    auto load_chunk = [&](int c, int stg) {
        const uint32_t base = sb + stg * STAGEB;
        const int k0 = c * 32;
        {
            uint32_t so = base + (uint32_t)(r0 * (TSROW * 2) + s0 * 16);
            size_t go = (size_t)r0 * 384 + k0 + s0 * 8;
            cp16(so,             Ahg + go);
            cp16(so + TILEB,     Alg + go);
            cp16(so + 2 * TILEB, Bhg + go);
            cp16(so + 3 * TILEB, Blg + go);
        }
        {
            uint32_t so = base + (uint32_t)(r1 * (TSROW * 2) + s1 * 16);
            size_t go = (size_t)r1 * 384 + k0 + s1 * 8;
            cp16(so,             Ahg + go);
            cp16(so + TILEB,     Alg + go);
            cp16(so + 2 * TILEB, Bhg + go);
            cp16(so + 3 * TILEB, Blg + go);
        }
        asm volatile("cp.async.commit_group;" ::: "memory");
    };

    // ldmatrix per-lane addressing
    const int rA = lane & 15, cA = (lane >> 4) << 3;
    const int rB = (lane & 7) + ((lane & 16) ? 8 : 0);
    const int cB = ((lane >> 3) & 1) << 3;

    load_chunk(0, 0);

    for (int c = 0; c < 12; c++) {
        if (c < 11) load_chunk(c + 1, (c + 1) & 1);
        if (c < 11) asm volatile("cp.async.wait_group 1;" ::: "memory");
        else        asm volatile("cp.async.wait_group 0;" ::: "memory");
        __syncthreads();

        const uint32_t base = sb + (c & 1) * STAGEB;
#pragma unroll
        for (int kk = 0; kk < 32; kk += 16) {
            uint32_t ax[4][4], bx[4][2];
            // ---- hh: load Ah + Bh fragments, 16 MMAs
#pragma unroll
            for (int i = 0; i < 4; i++) {
                uint32_t addr = base +
                    (uint32_t)((warpM * 64 + i * 16 + rA) * (TSROW * 2) + (kk + cA) * 2);
                ldm_x4(ax[i], addr);
            }
#pragma unroll
            for (int jj = 0; jj < 2; jj++) {
                uint32_t rr[4];
                uint32_t addr = base + 2 * TILEB +
                    (uint32_t)((warpN * 32 + jj * 16 + rB) * (TSROW * 2) + (kk + cB) * 2);
                ldm_x4(rr, addr);
                bx[2 * jj][0] = rr[0]; bx[2 * jj][1] = rr[1];
                bx[2 * jj + 1][0] = rr[2]; bx[2 * jj + 1][1] = rr[3];
            }
#pragma unroll
            for (int i = 0; i < 4; i++)
#pragma unroll
                for (int j = 0; j < 4; j++) mma16816(acc[i][j], ax[i], bx[j]);
            // ---- lh: reload A <- Al (B fragments reused), 16 MMAs
#pragma unroll
            for (int i = 0; i < 4; i++) {
                uint32_t addr = base + TILEB +
                    (uint32_t)((warpM * 64 + i * 16 + rA) * (TSROW * 2) + (kk + cA) * 2);
                ldm_x4(ax[i], addr);
            }
#pragma unroll
            for (int i = 0; i < 4; i++)
#pragma unroll
                for (int j = 0; j < 4; j++) mma16816(acc[i][j], ax[i], bx[j]);
            // ---- hl: reload A <- Ah, B <- Bl, 16 MMAs
#pragma unroll
            for (int i = 0; i < 4; i++) {
                uint32_t addr = base +
                    (uint32_t)((warpM * 64 + i * 16 + rA) * (TSROW * 2) + (kk + cA) * 2);
                ldm_x4(ax[i], addr);
            }
#pragma unroll
            for (int jj = 0; jj < 2; jj++) {
                uint32_t rr[4];
                uint32_t addr = base + 3 * TILEB +
                    (uint32_t)((warpN * 32 + jj * 16 + rB) * (TSROW * 2) + (kk + cB) * 2);
                ldm_x4(rr, addr);
                bx[2 * jj][0] = rr[0]; bx[2 * jj][1] = rr[1];
                bx[2 * jj + 1][0] = rr[2]; bx[2 * jj + 1][1] = rr[3];
            }
#pragma unroll
            for (int i = 0; i < 4; i++)
#pragma unroll
                for (int j = 0; j < 4; j++) mma16816(acc[i][j], ax[i], bx[j]);
        }
        __syncthreads();
    }

    // ---------------- epilogue ----------------
#pragma unroll
    for (int j = 0; j < 4; j++) {
        const int cg = colBase + warpN * 32 + j * 8 + 2 * (lane & 3);
#pragma unroll
        for (int i = 0; i < 4; i++) {
            const int m = rowBase + warpM * 64 + i * 16 + (lane >> 2);
            if (mode == 0) {
                int bb = m / NTOK, n = m % NTOK;
                float* dst;
                int d;
                if (cg < 384) {
                    dst = g_Q + (((size_t)bb * 12 + (cg >> 5)) * NTOK + n) * 32;
                    d = cg & 31;
                } else {
                    int j2 = cg - 384;
                    float* basep = (j2 >= 384) ? g_V : g_K;
                    dst = basep + (((size_t)bb * 12 + ((j2 >> 5) % 12)) * NTOK + n) * 32;
                    d = j2 & 31;
                }
                *(float2*)(dst + d)          = make_float2(acc[i][j][0], acc[i][j][1]);
                *(float2*)(dst + d + 8 * 32) = make_float2(acc[i][j][2], acc[i][j][3]);
            } else {
                float b0 = bias[cg], b1 = bias[cg + 1];
                *(float2*)(out + (size_t)m * 384 + cg) =
                    make_float2(acc[i][j][0] + b0, acc[i][j][1] + b1);
                *(float2*)(out + (size_t)(m + 8) * 384 + cg) =
                    make_float2(acc[i][j][2] + b0, acc[i][j][3] + b1);
            }
        }
    }
}

// ---------------- fused depthwise convs ------------------------------------------
__global__ void dwconv_fused(const float* __restrict__ w1, const float* __restrict__ b1,
                             const float* __restrict__ w2, const float* __restrict__ b2)
{
    int which = blockIdx.y % 3;          // 0=Q 1=K 2=V
    int op    = blockIdx.y / 3;          // 0=conv1 1=conv2
    const float* src = which == 0 ? g_Q : which == 1 ? g_K : g_V;
    int bg = blockIdx.x;
    int b = bg >> 2, hl = bg & 3;

    if (op == 0) {
        float* dst = which == 0 ? g_Q1 : which == 1 ? g_K1 : g_V1;
        const float* s = src + ((size_t)(b * 12 + 4 + hl)) * NTOK * 32;
        float* d = dst + (size_t)bg * 784 * 32;
        for (int idx = threadIdx.x; idx < 784 * 32; idx += blockDim.x) {
            int c = idx & 31;
            int xy = idx >> 5;
            int xo = xy % 28, yo = xy / 28;
            float acc = b1[c];
#pragma unroll
            for (int i = 0; i < 2; i++)
#pragma unroll
                for (int j = 0; j < 2; j++)
                    acc = fmaf(s[((2 * yo + i) * 56 + 2 * xo + j) * 32 + c],
                               w1[(i * 2 + j) * 32 + c], acc);
            d[idx] = acc;
        }
    } else {
        float* dst = which == 0 ? g_Q2 : which == 1 ? g_K2 : g_V2;
        const float* s = src + ((size_t)(b * 12 + 8 + hl)) * NTOK * 32;
        float* d = dst + (size_t)bg * 196 * 32;
        for (int idx = threadIdx.x; idx < 196 * 32; idx += blockDim.x) {
            int c = idx & 31;
            int xy = idx >> 5;
            int xo = xy % 14, yo = xy / 14;
            float acc = b2[c];
#pragma unroll
            for (int i = 0; i < 2; i++) {
                int iy = 4 * yo - 1 + 2 * i;
                if (iy < 0 || iy >= 56) continue;
#pragma unroll
                for (int j = 0; j < 2; j++) {
                    int ix = 4 * xo - 1 + 2 * j;
                    if (ix < 0 || ix >= 56) continue;
                    acc = fmaf(s[(iy * 56 + ix) * 32 + c], w2[(i * 2 + j) * 32 + c], acc);
                }
            }
            d[idx] = acc;
        }
    }
}

// ---------------- windowed attention: reg-cached K, batched PV -------------------
__global__ __launch_bounds__(256)
void window_attn(int scaleId)
{
    __shared__ __align__(16) float sQ[49 * 36];
    __shared__ __align__(16) float sK[64 * 36];
    __shared__ __align__(16) float sV[49 * 36];

    const float *Qb, *Kb, *Vb;
    int side, nside, headOff, ntile, seq;
    if (scaleId == 0)      { Qb = g_Q;  Kb = g_K;  Vb = g_V;  side = 56; nside = 8; headOff = 0; ntile = 1;  seq = 3136; }
    else if (scaleId == 1) { Qb = g_Q1; Kb = g_K1; Vb = g_V1; side = 28; nside = 4; headOff = 4; ntile = 4;  seq = 784;  }
    else                   { Qb = g_Q2; Kb = g_K2; Vb = g_V2; side = 14; nside = 2; headOff = 8; ntile = 16; seq = 196;  }

    const int nwin = nside * nside;
    const int rg = blockIdx.x % nwin;
    const int hl = (blockIdx.x / nwin) & 3;
    const int b  = blockIdx.x / (nwin * 4);
    const int hb = rg / nside, wb = rg % nside;

    const int imgIdx = (scaleId == 0) ? (b * 12 + hl) : (b * 4 + hl);
    const float* Qp = Qb + (size_t)imgIdx * seq * 32;
    const float* Kp = Kb + (size_t)imgIdx * seq * 32;
    const float* Vp = Vb + (size_t)imgIdx * seq * 32;

    for (int idx = threadIdx.x; idx < 49 * 32; idx += 256) {
        int p = idx >> 5, k = idx & 31;
        int yy = hb * 7 + p / 7, xx = wb * 7 + p % 7;
        int off = (yy * side + xx) * 32 + k;
        sQ[p * 36 + k] = Qp[off];
        sK[p * 36 + k] = Kp[off];
        sV[p * 36 + k] = Vp[off];
    }
    for (int idx = threadIdx.x; idx < 15 * 36; idx += 256)
        sK[49 * 36 + idx] = 0.f;
    __syncthreads();

    const int lane = threadIdx.x & 31;
    const int warp = threadIdx.x >> 5;
    const float scale = 0.17677669529663687f;
    const bool hi = (lane < 17);

    float4 kA[8], kB[8];
#pragma unroll
    for (int j = 0; j < 8; j++) {
        kA[j] = *(const float4*)&sK[lane * 36 + 4 * j];
        kB[j] = *(const float4*)&sK[(lane + 32) * 36 + 4 * j];
    }

    float e0v[7], e1v[7], rinv[7], accv[7];
#pragma unroll
    for (int i = 0; i < 7; i++) { e0v[i] = 0.f; e1v[i] = 0.f; rinv[i] = 0.f; accv[i] = 0.f; }

#pragma unroll
    for (int i = 0; i < 7; i++) {
        int p = warp + 8 * i;
        if (p < 49) {
            float s0 = 0.f, s1 = 0.f;
#pragma unroll
            for (int j = 0; j < 8; j++) {
                float4 qv = *(const float4*)&sQ[p * 36 + 4 * j];
                s0 = fmaf(qv.x, kA[j].x, s0); s0 = fmaf(qv.y, kA[j].y, s0);
                s0 = fmaf(qv.z, kA[j].z, s0); s0 = fmaf(qv.w, kA[j].w, s0);
                s1 = fmaf(qv.x, kB[j].x, s1); s1 = fmaf(qv.y, kB[j].y, s1);
                s1 = fmaf(qv.z, kB[j].z, s1); s1 = fmaf(qv.w, kB[j].w, s1);
            }
            float t0 = s0 * scale;
            float t1 = s1 * scale;
            float m = hi ? fmaxf(t0, t1) : t0;
#pragma unroll
            for (int o = 16; o > 0; o >>= 1) m = fmaxf(m, __shfl_xor_sync(0xffffffffu, m, o));
            float e0 = __expf(t0 - m);
            float e1 = hi ? __expf(t1 - m) : 0.f;
            float sum = e0 + e1;
#pragma unroll
            for (int o = 16; o > 0; o >>= 1) sum += __shfl_xor_sync(0xffffffffu, sum, o);
            e0v[i] = e0;
            e1v[i] = e1;
            rinv[i] = 1.f / sum;
        }
    }

    for (int q = 0; q < 49; q++) {
        float v = sV[q * 36 + lane];
        if (q < 32) {
#pragma unroll
            for (int i = 0; i < 7; i++) {
                float pq = __shfl_sync(0xffffffffu, e0v[i], q);
                accv[i] = fmaf(pq, v, accv[i]);
            }
        } else {
#pragma unroll
            for (int i = 0; i < 7; i++) {
                float pq = __shfl_sync(0xffffffffu, e1v[i], q - 32);
                accv[i] = fmaf(pq, v, accv[i]);
            }
        }
    }

#pragma unroll
    for (int i = 0; i < 7; i++) {
        int p = warp + 8 * i;
        if (p < 49) {
            float val = accv[i] * rinv[i];
            __nv_bfloat16 h = __float2bfloat16(val);
            __nv_bfloat16 l = __float2bfloat16(val - __bfloat162float(h));
            int col = (headOff + hl) * 32 + lane;
            for (int t = 0; t < ntile; t++) {
                int nout = (t * nwin + rg) * 49 + p;
                size_t off = ((size_t)b * NTOK + nout) * 384 + col;
                g_Zh[off] = h;
                g_Zl[off] = l;
            }
        }
    }
}

// ---------------- launch ---------------------------------------------------------
extern "C" void kernel_launch(void* const* d_in, const int* in_sizes, int n_in,
                              void* d_out, int out_size)
{
    const float* x     = (const float*)d_in[0];
    const float* Wq    = (const float*)d_in[1];
    const float* Wkv   = (const float*)d_in[2];
    const float* Wproj = (const float*)d_in[3];
    const float* bproj = (const float*)d_in[4];
    const float* c1w   = (const float*)d_in[5];
    const float* c1b   = (const float*)d_in[6];
    const float* c2w   = (const float*)d_in[7];
    const float* c2b   = (const float*)d_in[8];
    float* out = (float*)d_out;

    cudaFuncSetAttribute(gemm_mma, cudaFuncAttributeMaxDynamicSharedMemorySize, SMEM_GEMM);

    split_x<<<4704, 256>>>((const float4*)x);
    make_wt_qkv<<<1728, 256>>>(Wq, Wkv);
    make_wt_proj<<<576, 256>>>(Wproj);
    gemm_mma<<<dim3(9, 784), 256, SMEM_GEMM>>>(nullptr, nullptr, 0);   // 4th launch -> ncu
    dwconv_fused<<<dim3(128, 6), 256>>>(c1w, c1b, c2w, c2b);
    window_attn<<<32 * 4 * 64, 256>>>(0);
    window_attn<<<32 * 4 * 16, 256>>>(1);
    window_attn<<<32 * 4 * 4,  256>>>(2);
    gemm_mma<<<dim3(3, 784), 256, SMEM_GEMM>>>(bproj, out, 1);
}

// round 8
// speedup vs baseline: 1.2707x; 1.0032x over previous
#include <cuda_runtime.h>
#include <cuda_bf16.h>
#include <cstdint>

#define B_    32
#define NTOK  3136
#define NH    12
#define D_    32

// ---------------- scratch (device globals; no allocation allowed) -------------
__device__ __align__(16) float g_Q[(size_t)B_ * NH * NTOK * D_];   // [b*12+h][n][d]
__device__ __align__(16) float g_K[(size_t)B_ * NH * NTOK * D_];
__device__ __align__(16) float g_V[(size_t)B_ * NH * NTOK * D_];
__device__ __align__(16) float g_Q1[B_ * 4 * 784 * D_];
__device__ __align__(16) float g_K1[B_ * 4 * 784 * D_];
__device__ __align__(16) float g_V1[B_ * 4 * 784 * D_];
__device__ __align__(16) float g_Q2[B_ * 4 * 196 * D_];
__device__ __align__(16) float g_K2[B_ * 4 * 196 * D_];
__device__ __align__(16) float g_V2[B_ * 4 * 196 * D_];

#define XELEMS ((size_t)B_ * NTOK * 384)
__device__ __align__(16) __nv_bfloat16 g_Xh[XELEMS];
__device__ __align__(16) __nv_bfloat16 g_Xl[XELEMS];
__device__ __align__(16) __nv_bfloat16 g_Zh[XELEMS];
__device__ __align__(16) __nv_bfloat16 g_Zl[XELEMS];
// transposed weights, [n][k]: rows 0..1151 = qkv output cols, 1152..1535 = proj cols
__device__ __align__(16) __nv_bfloat16 g_WTh[1536 * 384];
__device__ __align__(16) __nv_bfloat16 g_WTl[1536 * 384];

// ---------------- helpers -------------------------------------------------------
__device__ __forceinline__ uint32_t smem_u32(const void* p) {
    uint32_t a;
    asm("{ .reg .u64 t; cvta.to.shared.u64 t, %1; cvt.u32.u64 %0, t; }" : "=r"(a) : "l"(p));
    return a;
}
__device__ __forceinline__ void cp16(uint32_t dst, const void* src) {
    asm volatile("cp.async.cg.shared.global [%0], [%1], 16;" :: "r"(dst), "l"(src));
}
__device__ __forceinline__ void ldm_x4(uint32_t* r, uint32_t a) {
    asm volatile("ldmatrix.sync.aligned.m8n8.x4.shared.b16 {%0,%1,%2,%3}, [%4];"
                 : "=r"(r[0]), "=r"(r[1]), "=r"(r[2]), "=r"(r[3]) : "r"(a));
}
__device__ __forceinline__ void mma16816(float* d, const uint32_t* a, const uint32_t* b) {
    asm volatile(
        "mma.sync.aligned.m16n8k16.row.col.f32.bf16.bf16.f32 "
        "{%0,%1,%2,%3}, {%4,%5,%6,%7}, {%8,%9}, {%0,%1,%2,%3};"
        : "+f"(d[0]), "+f"(d[1]), "+f"(d[2]), "+f"(d[3])
        : "r"(a[0]), "r"(a[1]), "r"(a[2]), "r"(a[3]), "r"(b[0]), "r"(b[1]));
}

// ---------------- split / transpose kernels ------------------------------------
__global__ void split_x(const float4* __restrict__ src) {
    uint2* hiP = (uint2*)g_Xh;
    uint2* loP = (uint2*)g_Xl;
    const int n4 = (int)(XELEMS / 4);
    const int stride = gridDim.x * blockDim.x;
    for (int i = blockIdx.x * blockDim.x + threadIdx.x; i < n4; i += stride) {
        float4 f = src[i];
        uint32_t x = __float_as_uint(f.x), y = __float_as_uint(f.y);
        uint32_t z = __float_as_uint(f.z), w = __float_as_uint(f.w);
        uint2 h;
        h.x = __byte_perm(x, y, 0x7632);
        h.y = __byte_perm(z, w, 0x7632);
        float l0 = f.x - __uint_as_float(x & 0xFFFF0000u);
        float l1 = f.y - __uint_as_float(y & 0xFFFF0000u);
        float l2 = f.z - __uint_as_float(z & 0xFFFF0000u);
        float l3 = f.w - __uint_as_float(w & 0xFFFF0000u);
        uint2 l;
        asm("cvt.rn.bf16x2.f32 %0, %1, %2;" : "=r"(l.x) : "f"(l1), "f"(l0));
        asm("cvt.rn.bf16x2.f32 %0, %1, %2;" : "=r"(l.y) : "f"(l3), "f"(l2));
        hiP[i] = h;
        loP[i] = l;
    }
}

__global__ void make_wt_qkv(const float* __restrict__ Wq, const float* __restrict__ Wkv) {
    int idx = blockIdx.x * 256 + threadIdx.x;
    if (idx >= 1152 * 384) return;
    int nrow = idx / 384, k = idx % 384;
    float v = (nrow < 384) ? Wq[(size_t)k * 384 + nrow]
                           : Wkv[(size_t)k * 768 + (nrow - 384)];
    uint32_t bits = __float_as_uint(v);
    float hf = __uint_as_float(bits & 0xFFFF0000u);
    g_WTh[idx] = __ushort_as_bfloat16((unsigned short)(bits >> 16));
    g_WTl[idx] = __float2bfloat16(v - hf);
}
__global__ void make_wt_proj(const float* __restrict__ Wproj) {
    int idx = blockIdx.x * 256 + threadIdx.x;
    if (idx >= 384 * 384) return;
    int nrow = idx / 384, k = idx % 384;
    float v = Wproj[(size_t)k * 384 + nrow];
    uint32_t bits = __float_as_uint(v);
    float hf = __uint_as_float(bits & 0xFFFF0000u);
    g_WTh[1152 * 384 + idx] = __ushort_as_bfloat16((unsigned short)(bits >> 16));
    g_WTl[1152 * 384 + idx] = __float2bfloat16(v - hf);
}

// ---------------- HMMA GEMM: 128x128 tile, chunk K=32, 2 stages -----------------
// smem tile: 128 rows x 32 bf16, row stride 40 bf16 (80B) -> conflict-free ldmatrix
#define TSROW 40
#define TILEB (128 * TSROW * 2)      // 10240
#define STAGEB (4 * TILEB)           // 40960 (Ah, Al, Bh, Bl)
#define SMEM_GEMM (2 * STAGEB)       // 81920

__global__ __launch_bounds__(256, 2)
void gemm_mma(const float* __restrict__ bias, float* __restrict__ out, int mode)
{
    extern __shared__ __align__(16) char smem[];
    const uint32_t sb = smem_u32(smem);
    const int tid = threadIdx.x, lane = tid & 31, wid = tid >> 5;
    const int warpM = wid & 1, warpN = wid >> 1;    // 2 x 4 warp grid
    const int rowBase = blockIdx.y * 128, colBase = blockIdx.x * 128;

    const __nv_bfloat16* Ahg = (mode == 0 ? g_Xh : g_Zh) + (size_t)rowBase * 384;
    const __nv_bfloat16* Alg = (mode == 0 ? g_Xl : g_Zl) + (size_t)rowBase * 384;
    const int brow = (mode == 0 ? 0 : 1152) + colBase;
    const __nv_bfloat16* Bhg = g_WTh + (size_t)brow * 384;
    const __nv_bfloat16* Blg = g_WTl + (size_t)brow * 384;

    const int r0 = tid >> 2, s0 = tid & 3;
    const int r1 = (tid + 256) >> 2, s1 = tid & 3;

    float acc[4][4][4];
#pragma unroll
    for (int i = 0; i < 4; i++)
#pragma unroll
        for (int j = 0; j < 4; j++)
#pragma unroll
            for (int q = 0; q < 4; q++) acc[i][j][q] = 0.f;

    auto load_chunk = [&](int c, int stg) {
        const uint32_t base = sb + stg * STAGEB;
        const int k0 = c * 32;
        {
            uint32_t so = base + (uint32_t)(r0 * (TSROW * 2) + s0 * 16);
            size_t go = (size_t)r0 * 384 + k0 + s0 * 8;
            cp16(so,             Ahg + go);
            cp16(so + TILEB,     Alg + go);
            cp16(so + 2 * TILEB, Bhg + go);
            cp16(so + 3 * TILEB, Blg + go);
        }
        {
            uint32_t so = base + (uint32_t)(r1 * (TSROW * 2) + s1 * 16);
            size_t go = (size_t)r1 * 384 + k0 + s1 * 8;
            cp16(so,             Ahg + go);
            cp16(so + TILEB,     Alg + go);
            cp16(so + 2 * TILEB, Bhg + go);
            cp16(so + 3 * TILEB, Blg + go);
        }
        asm volatile("cp.async.commit_group;" ::: "memory");
    };

    const int rA = lane & 15, cA = (lane >> 4) << 3;
    const int rB = (lane & 7) + ((lane & 16) ? 8 : 0);
    const int cB = ((lane >> 3) & 1) << 3;

    load_chunk(0, 0);

    for (int c = 0; c < 12; c++) {
        if (c < 11) load_chunk(c + 1, (c + 1) & 1);
        if (c < 11) asm volatile("cp.async.wait_group 1;" ::: "memory");
        else        asm volatile("cp.async.wait_group 0;" ::: "memory");
        __syncthreads();

        const uint32_t base = sb + (c & 1) * STAGEB;
#pragma unroll
        for (int kk = 0; kk < 32; kk += 16) {
            uint32_t ax[4][4], bx[4][2];
            // ---- hh: load Ah + Bh fragments, 16 MMAs
#pragma unroll
            for (int i = 0; i < 4; i++) {
                uint32_t addr = base +
                    (uint32_t)((warpM * 64 + i * 16 + rA) * (TSROW * 2) + (kk + cA) * 2);
                ldm_x4(ax[i], addr);
            }
#pragma unroll
            for (int jj = 0; jj < 2; jj++) {
                uint32_t rr[4];
                uint32_t addr = base + 2 * TILEB +
                    (uint32_t)((warpN * 32 + jj * 16 + rB) * (TSROW * 2) + (kk + cB) * 2);
                ldm_x4(rr, addr);
                bx[2 * jj][0] = rr[0]; bx[2 * jj][1] = rr[1];
                bx[2 * jj + 1][0] = rr[2]; bx[2 * jj + 1][1] = rr[3];
            }
#pragma unroll
            for (int i = 0; i < 4; i++)
#pragma unroll
                for (int j = 0; j < 4; j++) mma16816(acc[i][j], ax[i], bx[j]);
            // ---- hl: Ah fragments reused, B <- Bl, 16 MMAs
#pragma unroll
            for (int jj = 0; jj < 2; jj++) {
                uint32_t rr[4];
                uint32_t addr = base + 3 * TILEB +
                    (uint32_t)((warpN * 32 + jj * 16 + rB) * (TSROW * 2) + (kk + cB) * 2);
                ldm_x4(rr, addr);
                bx[2 * jj][0] = rr[0]; bx[2 * jj][1] = rr[1];
                bx[2 * jj + 1][0] = rr[2]; bx[2 * jj + 1][1] = rr[3];
            }
#pragma unroll
            for (int i = 0; i < 4; i++)
#pragma unroll
                for (int j = 0; j < 4; j++) mma16816(acc[i][j], ax[i], bx[j]);
            // ---- lh: A <- Al, B <- Bh (reload), 16 MMAs
#pragma unroll
            for (int i = 0; i < 4; i++) {
                uint32_t addr = base + TILEB +
                    (uint32_t)((warpM * 64 + i * 16 + rA) * (TSROW * 2) + (kk + cA) * 2);
                ldm_x4(ax[i], addr);
            }
#pragma unroll
            for (int jj = 0; jj < 2; jj++) {
                uint32_t rr[4];
                uint32_t addr = base + 2 * TILEB +
                    (uint32_t)((warpN * 32 + jj * 16 + rB) * (TSROW * 2) + (kk + cB) * 2);
                ldm_x4(rr, addr);
                bx[2 * jj][0] = rr[0]; bx[2 * jj][1] = rr[1];
                bx[2 * jj + 1][0] = rr[2]; bx[2 * jj + 1][1] = rr[3];
            }
#pragma unroll
            for (int i = 0; i < 4; i++)
#pragma unroll
                for (int j = 0; j < 4; j++) mma16816(acc[i][j], ax[i], bx[j]);
        }
        __syncthreads();
    }

    // ---------------- epilogue ----------------
#pragma unroll
    for (int j = 0; j < 4; j++) {
        const int cg = colBase + warpN * 32 + j * 8 + 2 * (lane & 3);
#pragma unroll
        for (int i = 0; i < 4; i++) {
            const int m = rowBase + warpM * 64 + i * 16 + (lane >> 2);
            if (mode == 0) {
                int bb = m / NTOK, n = m % NTOK;
                float* dst;
                int d;
                if (cg < 384) {
                    dst = g_Q + (((size_t)bb * 12 + (cg >> 5)) * NTOK + n) * 32;
                    d = cg & 31;
                } else {
                    int j2 = cg - 384;
                    float* basep = (j2 >= 384) ? g_V : g_K;
                    dst = basep + (((size_t)bb * 12 + ((j2 >> 5) % 12)) * NTOK + n) * 32;
                    d = j2 & 31;
                }
                *(float2*)(dst + d)          = make_float2(acc[i][j][0], acc[i][j][1]);
                *(float2*)(dst + d + 8 * 32) = make_float2(acc[i][j][2], acc[i][j][3]);
            } else {
                float b0 = bias[cg], b1 = bias[cg + 1];
                *(float2*)(out + (size_t)m * 384 + cg) =
                    make_float2(acc[i][j][0] + b0, acc[i][j][1] + b1);
                *(float2*)(out + (size_t)(m + 8) * 384 + cg) =
                    make_float2(acc[i][j][2] + b0, acc[i][j][3] + b1);
            }
        }
    }
}

// ---------------- fused depthwise convs ------------------------------------------
__global__ void dwconv_fused(const float* __restrict__ w1, const float* __restrict__ b1,
                             const float* __restrict__ w2, const float* __restrict__ b2)
{
    int which = blockIdx.y % 3;          // 0=Q 1=K 2=V
    int op    = blockIdx.y / 3;          // 0=conv1 1=conv2
    const float* src = which == 0 ? g_Q : which == 1 ? g_K : g_V;
    int bg = blockIdx.x;
    int b = bg >> 2, hl = bg & 3;

    if (op == 0) {
        float* dst = which == 0 ? g_Q1 : which == 1 ? g_K1 : g_V1;
        const float* s = src + ((size_t)(b * 12 + 4 + hl)) * NTOK * 32;
        float* d = dst + (size_t)bg * 784 * 32;
        for (int idx = threadIdx.x; idx < 784 * 32; idx += blockDim.x) {
            int c = idx & 31;
            int xy = idx >> 5;
            int xo = xy % 28, yo = xy / 28;
            float acc = b1[c];
#pragma unroll
            for (int i = 0; i < 2; i++)
#pragma unroll
                for (int j = 0; j < 2; j++)
                    acc = fmaf(s[((2 * yo + i) * 56 + 2 * xo + j) * 32 + c],
                               w1[(i * 2 + j) * 32 + c], acc);
            d[idx] = acc;
        }
    } else {
        float* dst = which == 0 ? g_Q2 : which == 1 ? g_K2 : g_V2;
        const float* s = src + ((size_t)(b * 12 + 8 + hl)) * NTOK * 32;
        float* d = dst + (size_t)bg * 196 * 32;
        for (int idx = threadIdx.x; idx < 196 * 32; idx += blockDim.x) {
            int c = idx & 31;
            int xy = idx >> 5;
            int xo = xy % 14, yo = xy / 14;
            float acc = b2[c];
#pragma unroll
            for (int i = 0; i < 2; i++) {
                int iy = 4 * yo - 1 + 2 * i;
                if (iy < 0 || iy >= 56) continue;
#pragma unroll
                for (int j = 0; j < 2; j++) {
                    int ix = 4 * xo - 1 + 2 * j;
                    if (ix < 0 || ix >= 56) continue;
                    acc = fmaf(s[(iy * 56 + ix) * 32 + c], w2[(i * 2 + j) * 32 + c], acc);
                }
            }
            d[idx] = acc;
        }
    }
}

// ---------------- windowed attention: reg-cached K, batched PV -------------------
__global__ __launch_bounds__(256)
void window_attn(int scaleId)
{
    __shared__ __align__(16) float sQ[49 * 36];
    __shared__ __align__(16) float sK[64 * 36];
    __shared__ __align__(16) float sV[49 * 36];

    const float *Qb, *Kb, *Vb;
    int side, nside, headOff, ntile, seq;
    if (scaleId == 0)      { Qb = g_Q;  Kb = g_K;  Vb = g_V;  side = 56; nside = 8; headOff = 0; ntile = 1;  seq = 3136; }
    else if (scaleId == 1) { Qb = g_Q1; Kb = g_K1; Vb = g_V1; side = 28; nside = 4; headOff = 4; ntile = 4;  seq = 784;  }
    else                   { Qb = g_Q2; Kb = g_K2; Vb = g_V2; side = 14; nside = 2; headOff = 8; ntile = 16; seq = 196;  }

    const int nwin = nside * nside;
    const int rg = blockIdx.x % nwin;
    const int hl = (blockIdx.x / nwin) & 3;
    const int b  = blockIdx.x / (nwin * 4);
    const int hb = rg / nside, wb = rg % nside;

    const int imgIdx = (scaleId == 0) ? (b * 12 + hl) : (b * 4 + hl);
    const float* Qp = Qb + (size_t)imgIdx * seq * 32;
    const float* Kp = Kb + (size_t)imgIdx * seq * 32;
    const float* Vp = Vb + (size_t)imgIdx * seq * 32;

    for (int idx = threadIdx.x; idx < 49 * 32; idx += 256) {
        int p = idx >> 5, k = idx & 31;
        int yy = hb * 7 + p / 7, xx = wb * 7 + p % 7;
        int off = (yy * side + xx) * 32 + k;
        sQ[p * 36 + k] = Qp[off];
        sK[p * 36 + k] = Kp[off];
        sV[p * 36 + k] = Vp[off];
    }
    for (int idx = threadIdx.x; idx < 15 * 36; idx += 256)
        sK[49 * 36 + idx] = 0.f;
    __syncthreads();

    const int lane = threadIdx.x & 31;
    const int warp = threadIdx.x >> 5;
    const float scale = 0.17677669529663687f;
    const bool hi = (lane < 17);

    float4 kA[8], kB[8];
#pragma unroll
    for (int j = 0; j < 8; j++) {
        kA[j] = *(const float4*)&sK[lane * 36 + 4 * j];
        kB[j] = *(const float4*)&sK[(lane + 32) * 36 + 4 * j];
    }

    float e0v[7], e1v[7], rinv[7], accv[7];
#pragma unroll
    for (int i = 0; i < 7; i++) { e0v[i] = 0.f; e1v[i] = 0.f; rinv[i] = 0.f; accv[i] = 0.f; }

#pragma unroll
    for (int i = 0; i < 7; i++) {
        int p = warp + 8 * i;
        if (p < 49) {
            float s0 = 0.f, s1 = 0.f;
#pragma unroll
            for (int j = 0; j < 8; j++) {
                float4 qv = *(const float4*)&sQ[p * 36 + 4 * j];
                s0 = fmaf(qv.x, kA[j].x, s0); s0 = fmaf(qv.y, kA[j].y, s0);
                s0 = fmaf(qv.z, kA[j].z, s0); s0 = fmaf(qv.w, kA[j].w, s0);
                s1 = fmaf(qv.x, kB[j].x, s1); s1 = fmaf(qv.y, kB[j].y, s1);
                s1 = fmaf(qv.z, kB[j].z, s1); s1 = fmaf(qv.w, kB[j].w, s1);
            }
            float t0 = s0 * scale;
            float t1 = s1 * scale;
            float m = hi ? fmaxf(t0, t1) : t0;
#pragma unroll
            for (int o = 16; o > 0; o >>= 1) m = fmaxf(m, __shfl_xor_sync(0xffffffffu, m, o));
            float e0 = __expf(t0 - m);
            float e1 = hi ? __expf(t1 - m) : 0.f;
            float sum = e0 + e1;
#pragma unroll
            for (int o = 16; o > 0; o >>= 1) sum += __shfl_xor_sync(0xffffffffu, sum, o);
            e0v[i] = e0;
            e1v[i] = e1;
            rinv[i] = 1.f / sum;
        }
    }

    for (int q = 0; q < 49; q++) {
        float v = sV[q * 36 + lane];
        if (q < 32) {
#pragma unroll
            for (int i = 0; i < 7; i++) {
                float pq = __shfl_sync(0xffffffffu, e0v[i], q);
                accv[i] = fmaf(pq, v, accv[i]);
            }
        } else {
#pragma unroll
            for (int i = 0; i < 7; i++) {
                float pq = __shfl_sync(0xffffffffu, e1v[i], q - 32);
                accv[i] = fmaf(pq, v, accv[i]);
            }
        }
    }

#pragma unroll
    for (int i = 0; i < 7; i++) {
        int p = warp + 8 * i;
        if (p < 49) {
            float val = accv[i] * rinv[i];
            __nv_bfloat16 h = __float2bfloat16(val);
            __nv_bfloat16 l = __float2bfloat16(val - __bfloat162float(h));
            int col = (headOff + hl) * 32 + lane;
            for (int t = 0; t < ntile; t++) {
                int nout = (t * nwin + rg) * 49 + p;
                size_t off = ((size_t)b * NTOK + nout) * 384 + col;
                g_Zh[off] = h;
                g_Zl[off] = l;
            }
        }
    }
}

// ---------------- launch ---------------------------------------------------------
extern "C" void kernel_launch(void* const* d_in, const int* in_sizes, int n_in,
                              void* d_out, int out_size)
{
    const float* x     = (const float*)d_in[0];
    const float* Wq    = (const float*)d_in[1];
    const float* Wkv   = (const float*)d_in[2];
    const float* Wproj = (const float*)d_in[3];
    const float* bproj = (const float*)d_in[4];
    const float* c1w   = (const float*)d_in[5];
    const float* c1b   = (const float*)d_in[6];
    const float* c2w   = (const float*)d_in[7];
    const float* c2b   = (const float*)d_in[8];
    float* out = (float*)d_out;

    cudaFuncSetAttribute(gemm_mma, cudaFuncAttributeMaxDynamicSharedMemorySize, SMEM_GEMM);

    split_x<<<4704, 256>>>((const float4*)x);
    make_wt_qkv<<<1728, 256>>>(Wq, Wkv);
    gemm_mma<<<dim3(9, 784), 256, SMEM_GEMM>>>(nullptr, nullptr, 0);
    window_attn<<<32 * 4 * 64, 256>>>(0);        // 4th launch -> ncu profiles attn0
    dwconv_fused<<<dim3(128, 6), 256>>>(c1w, c1b, c2w, c2b);
    window_attn<<<32 * 4 * 16, 256>>>(1);
    window_attn<<<32 * 4 * 4,  256>>>(2);
    make_wt_proj<<<576, 256>>>(Wproj);
    gemm_mma<<<dim3(3, 784), 256, SMEM_GEMM>>>(bproj, out, 1);
}

// round 9
// speedup vs baseline: 1.3512x; 1.0633x over previous
#include <cuda_runtime.h>
#include <cuda_bf16.h>
#include <cstdint>

#define B_    32
#define NTOK  3136
#define NH    12
#define D_    32

// ---------------- scratch (device globals; no allocation allowed) -------------
__device__ __align__(16) float g_Q[(size_t)B_ * NH * NTOK * D_];   // [b*12+h][n][d]
__device__ __align__(16) float g_K[(size_t)B_ * NH * NTOK * D_];
__device__ __align__(16) float g_V[(size_t)B_ * NH * NTOK * D_];
__device__ __align__(16) float g_Q1[B_ * 4 * 784 * D_];
__device__ __align__(16) float g_K1[B_ * 4 * 784 * D_];
__device__ __align__(16) float g_V1[B_ * 4 * 784 * D_];
__device__ __align__(16) float g_Q2[B_ * 4 * 196 * D_];
__device__ __align__(16) float g_K2[B_ * 4 * 196 * D_];
__device__ __align__(16) float g_V2[B_ * 4 * 196 * D_];

#define XELEMS ((size_t)B_ * NTOK * 384)
__device__ __align__(16) __nv_bfloat16 g_Xh[XELEMS];
__device__ __align__(16) __nv_bfloat16 g_Xl[XELEMS];
__device__ __align__(16) __nv_bfloat16 g_Zh[XELEMS];
__device__ __align__(16) __nv_bfloat16 g_Zl[XELEMS];
// transposed weights, [n][k]: rows 0..1151 = qkv output cols, 1152..1535 = proj cols
__device__ __align__(16) __nv_bfloat16 g_WTh[1536 * 384];
__device__ __align__(16) __nv_bfloat16 g_WTl[1536 * 384];

// ---------------- helpers -------------------------------------------------------
__device__ __forceinline__ uint32_t smem_u32(const void* p) {
    uint32_t a;
    asm("{ .reg .u64 t; cvta.to.shared.u64 t, %1; cvt.u32.u64 %0, t; }" : "=r"(a) : "l"(p));
    return a;
}
__device__ __forceinline__ void cp16(uint32_t dst, const void* src) {
    asm volatile("cp.async.cg.shared.global [%0], [%1], 16;" :: "r"(dst), "l"(src));
}
__device__ __forceinline__ void ldm_x4(uint32_t* r, uint32_t a) {
    asm volatile("ldmatrix.sync.aligned.m8n8.x4.shared.b16 {%0,%1,%2,%3}, [%4];"
                 : "=r"(r[0]), "=r"(r[1]), "=r"(r[2]), "=r"(r[3]) : "r"(a));
}
__device__ __forceinline__ void mma16816(float* d, const uint32_t* a, const uint32_t* b) {
    asm volatile(
        "mma.sync.aligned.m16n8k16.row.col.f32.bf16.bf16.f32 "
        "{%0,%1,%2,%3}, {%4,%5,%6,%7}, {%8,%9}, {%0,%1,%2,%3};"
        : "+f"(d[0]), "+f"(d[1]), "+f"(d[2]), "+f"(d[3])
        : "r"(a[0]), "r"(a[1]), "r"(a[2]), "r"(a[3]), "r"(b[0]), "r"(b[1]));
}

// ---------------- split / transpose kernels ------------------------------------
__global__ void split_x(const float4* __restrict__ src) {
    uint2* hiP = (uint2*)g_Xh;
    uint2* loP = (uint2*)g_Xl;
    const int n4 = (int)(XELEMS / 4);
    const int stride = gridDim.x * blockDim.x;
    for (int i = blockIdx.x * blockDim.x + threadIdx.x; i < n4; i += stride) {
        float4 f = src[i];
        uint32_t x = __float_as_uint(f.x), y = __float_as_uint(f.y);
        uint32_t z = __float_as_uint(f.z), w = __float_as_uint(f.w);
        uint2 h;
        h.x = __byte_perm(x, y, 0x7632);
        h.y = __byte_perm(z, w, 0x7632);
        float l0 = f.x - __uint_as_float(x & 0xFFFF0000u);
        float l1 = f.y - __uint_as_float(y & 0xFFFF0000u);
        float l2 = f.z - __uint_as_float(z & 0xFFFF0000u);
        float l3 = f.w - __uint_as_float(w & 0xFFFF0000u);
        uint2 l;
        asm("cvt.rn.bf16x2.f32 %0, %1, %2;" : "=r"(l.x) : "f"(l1), "f"(l0));
        asm("cvt.rn.bf16x2.f32 %0, %1, %2;" : "=r"(l.y) : "f"(l3), "f"(l2));
        hiP[i] = h;
        loP[i] = l;
    }
}

__global__ void make_wt_qkv(const float* __restrict__ Wq, const float* __restrict__ Wkv) {
    int idx = blockIdx.x * 256 + threadIdx.x;
    if (idx >= 1152 * 384) return;
    int nrow = idx / 384, k = idx % 384;
    float v = (nrow < 384) ? Wq[(size_t)k * 384 + nrow]
                           : Wkv[(size_t)k * 768 + (nrow - 384)];
    uint32_t bits = __float_as_uint(v);
    float hf = __uint_as_float(bits & 0xFFFF0000u);
    g_WTh[idx] = __ushort_as_bfloat16((unsigned short)(bits >> 16));
    g_WTl[idx] = __float2bfloat16(v - hf);
}
__global__ void make_wt_proj(const float* __restrict__ Wproj) {
    int idx = blockIdx.x * 256 + threadIdx.x;
    if (idx >= 384 * 384) return;
    int nrow = idx / 384, k = idx % 384;
    float v = Wproj[(size_t)k * 384 + nrow];
    uint32_t bits = __float_as_uint(v);
    float hf = __uint_as_float(bits & 0xFFFF0000u);
    g_WTh[1152 * 384 + idx] = __ushort_as_bfloat16((unsigned short)(bits >> 16));
    g_WTl[1152 * 384 + idx] = __float2bfloat16(v - hf);
}

// ---------------- HMMA GEMM: 128x128 tile, chunk K=32, 2 stages -----------------
// smem tile: 128 rows x 32 bf16, row stride 40 bf16 (80B) -> conflict-free ldmatrix
#define TSROW 40
#define TILEB (128 * TSROW * 2)      // 10240
#define STAGEB (4 * TILEB)           // 40960 (Ah, Al, Bh, Bl)
#define SMEM_GEMM (2 * STAGEB)       // 81920

__global__ __launch_bounds__(256, 2)
void gemm_mma(const float* __restrict__ bias, float* __restrict__ out, int mode)
{
    extern __shared__ __align__(16) char smem[];
    const uint32_t sb = smem_u32(smem);
    const int tid = threadIdx.x, lane = tid & 31, wid = tid >> 5;
    const int warpM = wid & 1, warpN = wid >> 1;    // 2 x 4 warp grid
    const int rowBase = blockIdx.y * 128, colBase = blockIdx.x * 128;

    const __nv_bfloat16* Ahg = (mode == 0 ? g_Xh : g_Zh) + (size_t)rowBase * 384;
    const __nv_bfloat16* Alg = (mode == 0 ? g_Xl : g_Zl) + (size_t)rowBase * 384;
    const int brow = (mode == 0 ? 0 : 1152) + colBase;
    const __nv_bfloat16* Bhg = g_WTh + (size_t)brow * 384;
    const __nv_bfloat16* Blg = g_WTl + (size_t)brow * 384;

    const int r0 = tid >> 2, s0 = tid & 3;
    const int r1 = (tid + 256) >> 2, s1 = tid & 3;

    float acc[4][4][4];
#pragma unroll
    for (int i = 0; i < 4; i++)
#pragma unroll
        for (int j = 0; j < 4; j++)
#pragma unroll
            for (int q = 0; q < 4; q++) acc[i][j][q] = 0.f;

    auto load_chunk = [&](int c, int stg) {
        const uint32_t base = sb + stg * STAGEB;
        const int k0 = c * 32;
        {
            uint32_t so = base + (uint32_t)(r0 * (TSROW * 2) + s0 * 16);
            size_t go = (size_t)r0 * 384 + k0 + s0 * 8;
            cp16(so,             Ahg + go);
            cp16(so + TILEB,     Alg + go);
            cp16(so + 2 * TILEB, Bhg + go);
            cp16(so + 3 * TILEB, Blg + go);
        }
        {
            uint32_t so = base + (uint32_t)(r1 * (TSROW * 2) + s1 * 16);
            size_t go = (size_t)r1 * 384 + k0 + s1 * 8;
            cp16(so,             Ahg + go);
            cp16(so + TILEB,     Alg + go);
            cp16(so + 2 * TILEB, Bhg + go);
            cp16(so + 3 * TILEB, Blg + go);
        }
        asm volatile("cp.async.commit_group;" ::: "memory");
    };

    const int rA = lane & 15, cA = (lane >> 4) << 3;
    const int rB = (lane & 7) + ((lane & 16) ? 8 : 0);
    const int cB = ((lane >> 3) & 1) << 3;

    load_chunk(0, 0);

    for (int c = 0; c < 12; c++) {
        if (c < 11) load_chunk(c + 1, (c + 1) & 1);
        if (c < 11) asm volatile("cp.async.wait_group 1;" ::: "memory");
        else        asm volatile("cp.async.wait_group 0;" ::: "memory");
        __syncthreads();

        const uint32_t base = sb + (c & 1) * STAGEB;
#pragma unroll
        for (int kk = 0; kk < 32; kk += 16) {
            uint32_t ax[4][4], bx[4][2];
            // ---- hh: load Ah + Bh fragments, 16 MMAs
#pragma unroll
            for (int i = 0; i < 4; i++) {
                uint32_t addr = base +
                    (uint32_t)((warpM * 64 + i * 16 + rA) * (TSROW * 2) + (kk + cA) * 2);
                ldm_x4(ax[i], addr);
            }
#pragma unroll
            for (int jj = 0; jj < 2; jj++) {
                uint32_t rr[4];
                uint32_t addr = base + 2 * TILEB +
                    (uint32_t)((warpN * 32 + jj * 16 + rB) * (TSROW * 2) + (kk + cB) * 2);
                ldm_x4(rr, addr);
                bx[2 * jj][0] = rr[0]; bx[2 * jj][1] = rr[1];
                bx[2 * jj + 1][0] = rr[2]; bx[2 * jj + 1][1] = rr[3];
            }
#pragma unroll
            for (int i = 0; i < 4; i++)
#pragma unroll
                for (int j = 0; j < 4; j++) mma16816(acc[i][j], ax[i], bx[j]);
            // ---- hl: Ah fragments reused, B <- Bl, 16 MMAs
#pragma unroll
            for (int jj = 0; jj < 2; jj++) {
                uint32_t rr[4];
                uint32_t addr = base + 3 * TILEB +
                    (uint32_t)((warpN * 32 + jj * 16 + rB) * (TSROW * 2) + (kk + cB) * 2);
                ldm_x4(rr, addr);
                bx[2 * jj][0] = rr[0]; bx[2 * jj][1] = rr[1];
                bx[2 * jj + 1][0] = rr[2]; bx[2 * jj + 1][1] = rr[3];
            }
#pragma unroll
            for (int i = 0; i < 4; i++)
#pragma unroll
                for (int j = 0; j < 4; j++) mma16816(acc[i][j], ax[i], bx[j]);
            // ---- lh: A <- Al, B <- Bh (reload), 16 MMAs
#pragma unroll
            for (int i = 0; i < 4; i++) {
                uint32_t addr = base + TILEB +
                    (uint32_t)((warpM * 64 + i * 16 + rA) * (TSROW * 2) + (kk + cA) * 2);
                ldm_x4(ax[i], addr);
            }
#pragma unroll
            for (int jj = 0; jj < 2; jj++) {
                uint32_t rr[4];
                uint32_t addr = base + 2 * TILEB +
                    (uint32_t)((warpN * 32 + jj * 16 + rB) * (TSROW * 2) + (kk + cB) * 2);
                ldm_x4(rr, addr);
                bx[2 * jj][0] = rr[0]; bx[2 * jj][1] = rr[1];
                bx[2 * jj + 1][0] = rr[2]; bx[2 * jj + 1][1] = rr[3];
            }
#pragma unroll
            for (int i = 0; i < 4; i++)
#pragma unroll
                for (int j = 0; j < 4; j++) mma16816(acc[i][j], ax[i], bx[j]);
        }
        // race-fix: no warp may start overwriting this stage (via next iter's
        // load_chunk) until every warp has finished consuming it.
        __syncthreads();
    }

    // ---------------- epilogue ----------------
#pragma unroll
    for (int j = 0; j < 4; j++) {
        const int cg = colBase + warpN * 32 + j * 8 + 2 * (lane & 3);
#pragma unroll
        for (int i = 0; i < 4; i++) {
            const int m = rowBase + warpM * 64 + i * 16 + (lane >> 2);
            if (mode == 0) {
                int bb = m / NTOK, n = m % NTOK;
                float* dst;
                int d;
                if (cg < 384) {
                    dst = g_Q + (((size_t)bb * 12 + (cg >> 5)) * NTOK + n) * 32;
                    d = cg & 31;
                } else {
                    int j2 = cg - 384;
                    float* basep = (j2 >= 384) ? g_V : g_K;
                    dst = basep + (((size_t)bb * 12 + ((j2 >> 5) % 12)) * NTOK + n) * 32;
                    d = j2 & 31;
                }
                *(float2*)(dst + d)          = make_float2(acc[i][j][0], acc[i][j][1]);
                *(float2*)(dst + d + 8 * 32) = make_float2(acc[i][j][2], acc[i][j][3]);
            } else {
                float b0 = bias[cg], b1 = bias[cg + 1];
                *(float2*)(out + (size_t)m * 384 + cg) =
                    make_float2(acc[i][j][0] + b0, acc[i][j][1] + b1);
                *(float2*)(out + (size_t)(m + 8) * 384 + cg) =
                    make_float2(acc[i][j][2] + b0, acc[i][j][3] + b1);
            }
        }
    }
}

// ---------------- fused depthwise convs ------------------------------------------
__global__ void dwconv_fused(const float* __restrict__ w1, const float* __restrict__ b1,
                             const float* __restrict__ w2, const float* __restrict__ b2)
{
    int which = blockIdx.y % 3;          // 0=Q 1=K 2=V
    int op    = blockIdx.y / 3;          // 0=conv1 1=conv2
    const float* src = which == 0 ? g_Q : which == 1 ? g_K : g_V;
    int bg = blockIdx.x;
    int b = bg >> 2, hl = bg & 3;

    if (op == 0) {
        float* dst = which == 0 ? g_Q1 : which == 1 ? g_K1 : g_V1;
        const float* s = src + ((size_t)(b * 12 + 4 + hl)) * NTOK * 32;
        float* d = dst + (size_t)bg * 784 * 32;
        for (int idx = threadIdx.x; idx < 784 * 32; idx += blockDim.x) {
            int c = idx & 31;
            int xy = idx >> 5;
            int xo = xy % 28, yo = xy / 28;
            float acc = b1[c];
#pragma unroll
            for (int i = 0; i < 2; i++)
#pragma unroll
                for (int j = 0; j < 2; j++)
                    acc = fmaf(s[((2 * yo + i) * 56 + 2 * xo + j) * 32 + c],
                               w1[(i * 2 + j) * 32 + c], acc);
            d[idx] = acc;
        }
    } else {
        float* dst = which == 0 ? g_Q2 : which == 1 ? g_K2 : g_V2;
        const float* s = src + ((size_t)(b * 12 + 8 + hl)) * NTOK * 32;
        float* d = dst + (size_t)bg * 196 * 32;
        for (int idx = threadIdx.x; idx < 196 * 32; idx += blockDim.x) {
            int c = idx & 31;
            int xy = idx >> 5;
            int xo = xy % 14, yo = xy / 14;
            float acc = b2[c];
#pragma unroll
            for (int i = 0; i < 2; i++) {
                int iy = 4 * yo - 1 + 2 * i;
                if (iy < 0 || iy >= 56) continue;
#pragma unroll
                for (int j = 0; j < 2; j++) {
                    int ix = 4 * xo - 1 + 2 * j;
                    if (ix < 0 || ix >= 56) continue;
                    acc = fmaf(s[(iy * 56 + ix) * 32 + c], w2[(i * 2 + j) * 32 + c], acc);
                }
            }
            d[idx] = acc;
        }
    }
}

// ---------------- windowed attention: batched reductions + smem-P float4 PV ------
__global__ __launch_bounds__(256)
void window_attn(int scaleId)
{
    __shared__ __align__(16) float sQ[49 * 36];
    __shared__ __align__(16) float sK[64 * 36];
    __shared__ __align__(16) float sV[52 * 36];   // rows 49..51 zeroed
    __shared__ __align__(16) float sP[49 * 52];   // cols 49..51 zeroed

    const float *Qb, *Kb, *Vb;
    int side, nside, headOff, ntile, seq;
    if (scaleId == 0)      { Qb = g_Q;  Kb = g_K;  Vb = g_V;  side = 56; nside = 8; headOff = 0; ntile = 1;  seq = 3136; }
    else if (scaleId == 1) { Qb = g_Q1; Kb = g_K1; Vb = g_V1; side = 28; nside = 4; headOff = 4; ntile = 4;  seq = 784;  }
    else                   { Qb = g_Q2; Kb = g_K2; Vb = g_V2; side = 14; nside = 2; headOff = 8; ntile = 16; seq = 196;  }

    const int nwin = nside * nside;
    const int rg = blockIdx.x % nwin;
    const int hl = (blockIdx.x / nwin) & 3;
    const int b  = blockIdx.x / (nwin * 4);
    const int hb = rg / nside, wb = rg % nside;

    const int imgIdx = (scaleId == 0) ? (b * 12 + hl) : (b * 4 + hl);
    const float* Qp = Qb + (size_t)imgIdx * seq * 32;
    const float* Kp = Kb + (size_t)imgIdx * seq * 32;
    const float* Vp = Vb + (size_t)imgIdx * seq * 32;

    for (int idx = threadIdx.x; idx < 49 * 32; idx += 256) {
        int p = idx >> 5, k = idx & 31;
        int yy = hb * 7 + p / 7, xx = wb * 7 + p % 7;
        int off = (yy * side + xx) * 32 + k;
        sQ[p * 36 + k] = Qp[off];
        sK[p * 36 + k] = Kp[off];
        sV[p * 36 + k] = Vp[off];
    }
    for (int idx = threadIdx.x; idx < 15 * 36; idx += 256) sK[49 * 36 + idx] = 0.f;
    for (int idx = threadIdx.x; idx < 3 * 36; idx += 256)  sV[49 * 36 + idx] = 0.f;
    for (int idx = threadIdx.x; idx < 49 * 3; idx += 256)
        sP[(idx / 3) * 52 + 49 + (idx % 3)] = 0.f;
    __syncthreads();

    const int lane = threadIdx.x & 31;
    const int warp = threadIdx.x >> 5;
    const float scale = 0.17677669529663687f;
    const bool hi = (lane < 17);

    // each lane caches K rows (lane) and (lane+32)
    float4 kA[8], kB[8];
#pragma unroll
    for (int j = 0; j < 8; j++) {
        kA[j] = *(const float4*)&sK[lane * 36 + 4 * j];
        kB[j] = *(const float4*)&sK[(lane + 32) * 36 + 4 * j];
    }

    // --- QK: compute all 7 rows first (batched) ---
    float s0v[7], s1v[7];
#pragma unroll
    for (int i = 0; i < 7; i++) {
        int p = warp + 8 * i;
        float s0 = 0.f, s1 = 0.f;
        if (p < 49) {
#pragma unroll
            for (int j = 0; j < 8; j++) {
                float4 qv = *(const float4*)&sQ[p * 36 + 4 * j];
                s0 = fmaf(qv.x, kA[j].x, s0); s0 = fmaf(qv.y, kA[j].y, s0);
                s0 = fmaf(qv.z, kA[j].z, s0); s0 = fmaf(qv.w, kA[j].w, s0);
                s1 = fmaf(qv.x, kB[j].x, s1); s1 = fmaf(qv.y, kB[j].y, s1);
                s1 = fmaf(qv.z, kB[j].z, s1); s1 = fmaf(qv.w, kB[j].w, s1);
            }
        }
        s0v[i] = s0 * scale;
        s1v[i] = s1 * scale;
    }

    // --- batched (pipelined) max reductions across the 7 independent rows ---
    float mx[7];
#pragma unroll
    for (int i = 0; i < 7; i++) mx[i] = hi ? fmaxf(s0v[i], s1v[i]) : s0v[i];
#pragma unroll
    for (int o = 16; o > 0; o >>= 1) {
#pragma unroll
        for (int i = 0; i < 7; i++)
            mx[i] = fmaxf(mx[i], __shfl_xor_sync(0xffffffffu, mx[i], o));
    }
    float e0a[7], e1a[7], sm[7];
#pragma unroll
    for (int i = 0; i < 7; i++) {
        e0a[i] = __expf(s0v[i] - mx[i]);
        e1a[i] = hi ? __expf(s1v[i] - mx[i]) : 0.f;
        sm[i] = e0a[i] + e1a[i];
    }
#pragma unroll
    for (int o = 16; o > 0; o >>= 1) {
#pragma unroll
        for (int i = 0; i < 7; i++)
            sm[i] += __shfl_xor_sync(0xffffffffu, sm[i], o);
    }
    float rinv[7];
#pragma unroll
    for (int i = 0; i < 7; i++) {
        rinv[i] = 1.f / sm[i];
        int p = warp + 8 * i;
        if (p < 49) {
            sP[p * 52 + lane] = e0a[i];
            if (lane < 17) sP[p * 52 + 32 + lane] = e1a[i];
        }
    }
    __syncthreads();

    // --- PV: float4 prob reads from smem, V amortized across the 7 rows ---
    float accv[7];
#pragma unroll
    for (int i = 0; i < 7; i++) accv[i] = 0.f;
#pragma unroll
    for (int j = 0; j < 13; j++) {
        float4 pv[7];
#pragma unroll
        for (int i = 0; i < 7; i++) {
            int p = warp + 8 * i;
            pv[i] = (p < 49) ? *(const float4*)&sP[p * 52 + 4 * j]
                             : make_float4(0.f, 0.f, 0.f, 0.f);
        }
        {
            float v0 = sV[(4 * j + 0) * 36 + lane];
#pragma unroll
            for (int i = 0; i < 7; i++) accv[i] = fmaf(pv[i].x, v0, accv[i]);
            float v1 = sV[(4 * j + 1) * 36 + lane];
#pragma unroll
            for (int i = 0; i < 7; i++) accv[i] = fmaf(pv[i].y, v1, accv[i]);
            float v2 = sV[(4 * j + 2) * 36 + lane];
#pragma unroll
            for (int i = 0; i < 7; i++) accv[i] = fmaf(pv[i].z, v2, accv[i]);
            float v3 = sV[(4 * j + 3) * 36 + lane];
#pragma unroll
            for (int i = 0; i < 7; i++) accv[i] = fmaf(pv[i].w, v3, accv[i]);
        }
    }

#pragma unroll
    for (int i = 0; i < 7; i++) {
        int p = warp + 8 * i;
        if (p < 49) {
            float val = accv[i] * rinv[i];
            __nv_bfloat16 h = __float2bfloat16(val);
            __nv_bfloat16 l = __float2bfloat16(val - __bfloat162float(h));
            int col = (headOff + hl) * 32 + lane;
            for (int t = 0; t < ntile; t++) {
                int nout = (t * nwin + rg) * 49 + p;
                size_t off = ((size_t)b * NTOK + nout) * 384 + col;
                g_Zh[off] = h;
                g_Zl[off] = l;
            }
        }
    }
}

// ---------------- launch ---------------------------------------------------------
extern "C" void kernel_launch(void* const* d_in, const int* in_sizes, int n_in,
                              void* d_out, int out_size)
{
    const float* x     = (const float*)d_in[0];
    const float* Wq    = (const float*)d_in[1];
    const float* Wkv   = (const float*)d_in[2];
    const float* Wproj = (const float*)d_in[3];
    const float* bproj = (const float*)d_in[4];
    const float* c1w   = (const float*)d_in[5];
    const float* c1b   = (const float*)d_in[6];
    const float* c2w   = (const float*)d_in[7];
    const float* c2b   = (const float*)d_in[8];
    float* out = (float*)d_out;

    cudaFuncSetAttribute(gemm_mma, cudaFuncAttributeMaxDynamicSharedMemorySize, SMEM_GEMM);

    split_x<<<4704, 256>>>((const float4*)x);
    make_wt_qkv<<<1728, 256>>>(Wq, Wkv);
    gemm_mma<<<dim3(9, 784), 256, SMEM_GEMM>>>(nullptr, nullptr, 0);
    window_attn<<<32 * 4 * 64, 256>>>(0);        // 4th launch -> ncu profiles attn0
    dwconv_fused<<<dim3(128, 6), 256>>>(c1w, c1b, c2w, c2b);
    window_attn<<<32 * 4 * 16, 256>>>(1);
    window_attn<<<32 * 4 * 4,  256>>>(2);
    make_wt_proj<<<576, 256>>>(Wproj);
    gemm_mma<<<dim3(3, 784), 256, SMEM_GEMM>>>(bproj, out, 1);
}

// round 10
// speedup vs baseline: 1.5193x; 1.1244x over previous
#include <cuda_runtime.h>
#include <cuda_bf16.h>
#include <cstdint>

#define B_    32
#define NTOK  3136
#define NH    12
#define D_    32

// ---------------- scratch (device globals; no allocation allowed) -------------
__device__ __align__(16) float g_Q[(size_t)B_ * NH * NTOK * D_];   // [b*12+h][n][d]
__device__ __align__(16) float g_K[(size_t)B_ * NH * NTOK * D_];
__device__ __align__(16) float g_V[(size_t)B_ * NH * NTOK * D_];
__device__ __align__(16) float g_Q1[B_ * 4 * 784 * D_];
__device__ __align__(16) float g_K1[B_ * 4 * 784 * D_];
__device__ __align__(16) float g_V1[B_ * 4 * 784 * D_];
__device__ __align__(16) float g_Q2[B_ * 4 * 196 * D_];
__device__ __align__(16) float g_K2[B_ * 4 * 196 * D_];
__device__ __align__(16) float g_V2[B_ * 4 * 196 * D_];

#define XELEMS ((size_t)B_ * NTOK * 384)
__device__ __align__(16) __nv_bfloat16 g_Xh[XELEMS];
__device__ __align__(16) __nv_bfloat16 g_Xl[XELEMS];
__device__ __align__(16) __nv_bfloat16 g_Zh[XELEMS];
__device__ __align__(16) __nv_bfloat16 g_Zl[XELEMS];
// transposed weights, [n][k]: rows 0..1151 = qkv output cols, 1152..1535 = proj cols
__device__ __align__(16) __nv_bfloat16 g_WTh[1536 * 384];
__device__ __align__(16) __nv_bfloat16 g_WTl[1536 * 384];

// ---------------- helpers -------------------------------------------------------
__device__ __forceinline__ uint32_t smem_u32(const void* p) {
    uint32_t a;
    asm("{ .reg .u64 t; cvta.to.shared.u64 t, %1; cvt.u32.u64 %0, t; }" : "=r"(a) : "l"(p));
    return a;
}
__device__ __forceinline__ void cp16(uint32_t dst, const void* src) {
    asm volatile("cp.async.cg.shared.global [%0], [%1], 16;" :: "r"(dst), "l"(src));
}
__device__ __forceinline__ void ldm_x4(uint32_t* r, uint32_t a) {
    asm volatile("ldmatrix.sync.aligned.m8n8.x4.shared.b16 {%0,%1,%2,%3}, [%4];"
                 : "=r"(r[0]), "=r"(r[1]), "=r"(r[2]), "=r"(r[3]) : "r"(a));
}
__device__ __forceinline__ void mma16816(float* d, const uint32_t* a, const uint32_t* b) {
    asm volatile(
        "mma.sync.aligned.m16n8k16.row.col.f32.bf16.bf16.f32 "
        "{%0,%1,%2,%3}, {%4,%5,%6,%7}, {%8,%9}, {%0,%1,%2,%3};"
        : "+f"(d[0]), "+f"(d[1]), "+f"(d[2]), "+f"(d[3])
        : "r"(a[0]), "r"(a[1]), "r"(a[2]), "r"(a[3]), "r"(b[0]), "r"(b[1]));
}

// ---------------- split / transpose kernels ------------------------------------
__global__ void split_x(const float4* __restrict__ src) {
    uint2* hiP = (uint2*)g_Xh;
    uint2* loP = (uint2*)g_Xl;
    const int n4 = (int)(XELEMS / 4);
    const int stride = gridDim.x * blockDim.x;
    for (int i = blockIdx.x * blockDim.x + threadIdx.x; i < n4; i += stride) {
        float4 f = src[i];
        uint32_t x = __float_as_uint(f.x), y = __float_as_uint(f.y);
        uint32_t z = __float_as_uint(f.z), w = __float_as_uint(f.w);
        uint2 h;
        h.x = __byte_perm(x, y, 0x7632);
        h.y = __byte_perm(z, w, 0x7632);
        float l0 = f.x - __uint_as_float(x & 0xFFFF0000u);
        float l1 = f.y - __uint_as_float(y & 0xFFFF0000u);
        float l2 = f.z - __uint_as_float(z & 0xFFFF0000u);
        float l3 = f.w - __uint_as_float(w & 0xFFFF0000u);
        uint2 l;
        asm("cvt.rn.bf16x2.f32 %0, %1, %2;" : "=r"(l.x) : "f"(l1), "f"(l0));
        asm("cvt.rn.bf16x2.f32 %0, %1, %2;" : "=r"(l.y) : "f"(l3), "f"(l2));
        hiP[i] = h;
        loP[i] = l;
    }
}

__global__ void make_wt_qkv(const float* __restrict__ Wq, const float* __restrict__ Wkv) {
    int idx = blockIdx.x * 256 + threadIdx.x;
    if (idx >= 1152 * 384) return;
    int nrow = idx / 384, k = idx % 384;
    float v = (nrow < 384) ? Wq[(size_t)k * 384 + nrow]
                           : Wkv[(size_t)k * 768 + (nrow - 384)];
    uint32_t bits = __float_as_uint(v);
    float hf = __uint_as_float(bits & 0xFFFF0000u);
    g_WTh[idx] = __ushort_as_bfloat16((unsigned short)(bits >> 16));
    g_WTl[idx] = __float2bfloat16(v - hf);
}
__global__ void make_wt_proj(const float* __restrict__ Wproj) {
    int idx = blockIdx.x * 256 + threadIdx.x;
    if (idx >= 384 * 384) return;
    int nrow = idx / 384, k = idx % 384;
    float v = Wproj[(size_t)k * 384 + nrow];
    uint32_t bits = __float_as_uint(v);
    float hf = __uint_as_float(bits & 0xFFFF0000u);
    g_WTh[1152 * 384 + idx] = __ushort_as_bfloat16((unsigned short)(bits >> 16));
    g_WTl[1152 * 384 + idx] = __float2bfloat16(v - hf);
}

// ---------------- HMMA GEMM: 128x128 tile, chunk K=32, 3-stage ring, swizzled ---
// smem rows = 64B (4 x 16B segs); seg' = seg ^ ((row>>1)&3) -> conflict-free LDSM
#define BUFB   (128 * 64)            // 8192 bytes per operand buffer
#define STAGEB (4 * BUFB)            // 32768 (Ah, Al, Bh, Bl)
#define SMEM_GEMM (3 * STAGEB)       // 98304

__device__ __forceinline__ uint32_t swz(int row, int seg) {
    return (uint32_t)(row * 64 + ((seg ^ ((row >> 1) & 3)) << 4));
}

__global__ __launch_bounds__(256, 2)
void gemm_mma(const float* __restrict__ bias, float* __restrict__ out, int mode)
{
    extern __shared__ __align__(16) char smem[];
    const uint32_t sb = smem_u32(smem);
    const int tid = threadIdx.x, lane = tid & 31, wid = tid >> 5;
    const int warpM = wid & 1, warpN = wid >> 1;    // 2 x 4 warp grid
    const int rowBase = blockIdx.y * 128, colBase = blockIdx.x * 128;

    const __nv_bfloat16* Ahg = (mode == 0 ? g_Xh : g_Zh) + (size_t)rowBase * 384;
    const __nv_bfloat16* Alg = (mode == 0 ? g_Xl : g_Zl) + (size_t)rowBase * 384;
    const int brow = (mode == 0 ? 0 : 1152) + colBase;
    const __nv_bfloat16* Bhg = g_WTh + (size_t)brow * 384;
    const __nv_bfloat16* Blg = g_WTl + (size_t)brow * 384;

    // loader coords: thread covers rows lr and lr+64, seg lc (2 segs per buffer)
    const int lr = tid >> 2, lc = tid & 3;
    const uint32_t d0 = swz(lr, lc);
    const uint32_t d1 = swz(lr + 64, lc);

    float acc[4][4][4];
#pragma unroll
    for (int i = 0; i < 4; i++)
#pragma unroll
        for (int j = 0; j < 4; j++)
#pragma unroll
            for (int q = 0; q < 4; q++) acc[i][j][q] = 0.f;

    auto load_chunk = [&](int c, int stg) {
        const uint32_t base = sb + stg * STAGEB;
        const size_t g0 = (size_t)lr * 384 + c * 32 + lc * 8;
        const size_t g1 = (size_t)(lr + 64) * 384 + c * 32 + lc * 8;
        cp16(base + d0,             Ahg + g0);
        cp16(base + d1,             Ahg + g1);
        cp16(base + BUFB + d0,      Alg + g0);
        cp16(base + BUFB + d1,      Alg + g1);
        cp16(base + 2 * BUFB + d0,  Bhg + g0);
        cp16(base + 2 * BUFB + d1,  Bhg + g1);
        cp16(base + 3 * BUFB + d0,  Blg + g0);
        cp16(base + 3 * BUFB + d1,  Blg + g1);
        asm volatile("cp.async.commit_group;" ::: "memory");
    };

    // ldmatrix per-lane addressing (within a 16-row x 4-seg block)
    const int rA = lane & 15;
    const int sA_hi = (lane >> 4) & 1;              // +1 seg for lanes 16..31
    const int rB = (lane & 7) + ((lane & 16) ? 8 : 0);
    const int sB_hi = (lane >> 3) & 1;

    load_chunk(0, 0);
    load_chunk(1, 1);

    for (int c = 0; c < 12; c++) {
        if (c < 11) asm volatile("cp.async.wait_group 1;" ::: "memory");
        else        asm volatile("cp.async.wait_group 0;" ::: "memory");
        __syncthreads();
        // safe: the stage written here (chunk c+2) was fully consumed by every
        // warp at iter c-1, which precedes this barrier in program order.
        if (c + 2 < 12) load_chunk(c + 2, (c + 2) % 3);

        const uint32_t base = sb + (c % 3) * STAGEB;
#pragma unroll
        for (int kk = 0; kk < 32; kk += 16) {
            const int sA = (kk >> 3) + sA_hi;       // seg 0..3
            const int sB = (kk >> 3) + sB_hi;
            uint32_t ax[4][4], bx[4][2];
            // ---- hh: load Ah + Bh fragments, 16 MMAs
#pragma unroll
            for (int i = 0; i < 4; i++)
                ldm_x4(ax[i], base + swz(warpM * 64 + i * 16 + rA, sA));
#pragma unroll
            for (int jj = 0; jj < 2; jj++) {
                uint32_t rr[4];
                ldm_x4(rr, base + 2 * BUFB + swz(warpN * 32 + jj * 16 + rB, sB));
                bx[2 * jj][0] = rr[0]; bx[2 * jj][1] = rr[1];
                bx[2 * jj + 1][0] = rr[2]; bx[2 * jj + 1][1] = rr[3];
            }
#pragma unroll
            for (int i = 0; i < 4; i++)
#pragma unroll
                for (int j = 0; j < 4; j++) mma16816(acc[i][j], ax[i], bx[j]);
            // ---- hl: Ah fragments reused, B <- Bl, 16 MMAs
#pragma unroll
            for (int jj = 0; jj < 2; jj++) {
                uint32_t rr[4];
                ldm_x4(rr, base + 3 * BUFB + swz(warpN * 32 + jj * 16 + rB, sB));
                bx[2 * jj][0] = rr[0]; bx[2 * jj][1] = rr[1];
                bx[2 * jj + 1][0] = rr[2]; bx[2 * jj + 1][1] = rr[3];
            }
#pragma unroll
            for (int i = 0; i < 4; i++)
#pragma unroll
                for (int j = 0; j < 4; j++) mma16816(acc[i][j], ax[i], bx[j]);
            // ---- lh: A <- Al, B <- Bh (reload), 16 MMAs
#pragma unroll
            for (int i = 0; i < 4; i++)
                ldm_x4(ax[i], base + BUFB + swz(warpM * 64 + i * 16 + rA, sA));
#pragma unroll
            for (int jj = 0; jj < 2; jj++) {
                uint32_t rr[4];
                ldm_x4(rr, base + 2 * BUFB + swz(warpN * 32 + jj * 16 + rB, sB));
                bx[2 * jj][0] = rr[0]; bx[2 * jj][1] = rr[1];
                bx[2 * jj + 1][0] = rr[2]; bx[2 * jj + 1][1] = rr[3];
            }
#pragma unroll
            for (int i = 0; i < 4; i++)
#pragma unroll
                for (int j = 0; j < 4; j++) mma16816(acc[i][j], ax[i], bx[j]);
        }
    }

    // ---------------- epilogue ----------------
#pragma unroll
    for (int j = 0; j < 4; j++) {
        const int cg = colBase + warpN * 32 + j * 8 + 2 * (lane & 3);
#pragma unroll
        for (int i = 0; i < 4; i++) {
            const int m = rowBase + warpM * 64 + i * 16 + (lane >> 2);
            if (mode == 0) {
                int bb = m / NTOK, n = m % NTOK;
                float* dst;
                int d;
                if (cg < 384) {
                    dst = g_Q + (((size_t)bb * 12 + (cg >> 5)) * NTOK + n) * 32;
                    d = cg & 31;
                } else {
                    int j2 = cg - 384;
                    float* basep = (j2 >= 384) ? g_V : g_K;
                    dst = basep + (((size_t)bb * 12 + ((j2 >> 5) % 12)) * NTOK + n) * 32;
                    d = j2 & 31;
                }
                *(float2*)(dst + d)          = make_float2(acc[i][j][0], acc[i][j][1]);
                *(float2*)(dst + d + 8 * 32) = make_float2(acc[i][j][2], acc[i][j][3]);
            } else {
                float b0 = bias[cg], b1 = bias[cg + 1];
                *(float2*)(out + (size_t)m * 384 + cg) =
                    make_float2(acc[i][j][0] + b0, acc[i][j][1] + b1);
                *(float2*)(out + (size_t)(m + 8) * 384 + cg) =
                    make_float2(acc[i][j][2] + b0, acc[i][j][3] + b1);
            }
        }
    }
}

// ---------------- fused depthwise convs ------------------------------------------
__global__ void dwconv_fused(const float* __restrict__ w1, const float* __restrict__ b1,
                             const float* __restrict__ w2, const float* __restrict__ b2)
{
    int which = blockIdx.y % 3;          // 0=Q 1=K 2=V
    int op    = blockIdx.y / 3;          // 0=conv1 1=conv2
    const float* src = which == 0 ? g_Q : which == 1 ? g_K : g_V;
    int bg = blockIdx.x;
    int b = bg >> 2, hl = bg & 3;

    if (op == 0) {
        float* dst = which == 0 ? g_Q1 : which == 1 ? g_K1 : g_V1;
        const float* s = src + ((size_t)(b * 12 + 4 + hl)) * NTOK * 32;
        float* d = dst + (size_t)bg * 784 * 32;
        for (int idx = threadIdx.x; idx < 784 * 32; idx += blockDim.x) {
            int c = idx & 31;
            int xy = idx >> 5;
            int xo = xy % 28, yo = xy / 28;
            float acc = b1[c];
#pragma unroll
            for (int i = 0; i < 2; i++)
#pragma unroll
                for (int j = 0; j < 2; j++)
                    acc = fmaf(s[((2 * yo + i) * 56 + 2 * xo + j) * 32 + c],
                               w1[(i * 2 + j) * 32 + c], acc);
            d[idx] = acc;
        }
    } else {
        float* dst = which == 0 ? g_Q2 : which == 1 ? g_K2 : g_V2;
        const float* s = src + ((size_t)(b * 12 + 8 + hl)) * NTOK * 32;
        float* d = dst + (size_t)bg * 196 * 32;
        for (int idx = threadIdx.x; idx < 196 * 32; idx += blockDim.x) {
            int c = idx & 31;
            int xy = idx >> 5;
            int xo = xy % 14, yo = xy / 14;
            float acc = b2[c];
#pragma unroll
            for (int i = 0; i < 2; i++) {
                int iy = 4 * yo - 1 + 2 * i;
                if (iy < 0 || iy >= 56) continue;
#pragma unroll
                for (int j = 0; j < 2; j++) {
                    int ix = 4 * xo - 1 + 2 * j;
                    if (ix < 0 || ix >= 56) continue;
                    acc = fmaf(s[(iy * 56 + ix) * 32 + c], w2[(i * 2 + j) * 32 + c], acc);
                }
            }
            d[idx] = acc;
        }
    }
}

// ---------------- windowed attention: batched reductions + smem-P float4 PV ------
__global__ __launch_bounds__(256)
void window_attn(int scaleId)
{
    __shared__ __align__(16) float sQ[49 * 36];
    __shared__ __align__(16) float sK[64 * 36];
    __shared__ __align__(16) float sV[52 * 36];   // rows 49..51 zeroed
    __shared__ __align__(16) float sP[49 * 52];   // cols 49..51 zeroed

    const float *Qb, *Kb, *Vb;
    int side, nside, headOff, ntile, seq;
    if (scaleId == 0)      { Qb = g_Q;  Kb = g_K;  Vb = g_V;  side = 56; nside = 8; headOff = 0; ntile = 1;  seq = 3136; }
    else if (scaleId == 1) { Qb = g_Q1; Kb = g_K1; Vb = g_V1; side = 28; nside = 4; headOff = 4; ntile = 4;  seq = 784;  }
    else                   { Qb = g_Q2; Kb = g_K2; Vb = g_V2; side = 14; nside = 2; headOff = 8; ntile = 16; seq = 196;  }

    const int nwin = nside * nside;
    const int rg = blockIdx.x % nwin;
    const int hl = (blockIdx.x / nwin) & 3;
    const int b  = blockIdx.x / (nwin * 4);
    const int hb = rg / nside, wb = rg % nside;

    const int imgIdx = (scaleId == 0) ? (b * 12 + hl) : (b * 4 + hl);
    const float* Qp = Qb + (size_t)imgIdx * seq * 32;
    const float* Kp = Kb + (size_t)imgIdx * seq * 32;
    const float* Vp = Vb + (size_t)imgIdx * seq * 32;

    for (int idx = threadIdx.x; idx < 49 * 32; idx += 256) {
        int p = idx >> 5, k = idx & 31;
        int yy = hb * 7 + p / 7, xx = wb * 7 + p % 7;
        int off = (yy * side + xx) * 32 + k;
        sQ[p * 36 + k] = Qp[off];
        sK[p * 36 + k] = Kp[off];
        sV[p * 36 + k] = Vp[off];
    }
    for (int idx = threadIdx.x; idx < 15 * 36; idx += 256) sK[49 * 36 + idx] = 0.f;
    for (int idx = threadIdx.x; idx < 3 * 36; idx += 256)  sV[49 * 36 + idx] = 0.f;
    for (int idx = threadIdx.x; idx < 49 * 3; idx += 256)
        sP[(idx / 3) * 52 + 49 + (idx % 3)] = 0.f;
    __syncthreads();

    const int lane = threadIdx.x & 31;
    const int warp = threadIdx.x >> 5;
    const float scale = 0.17677669529663687f;
    const bool hi = (lane < 17);

    float4 kA[8], kB[8];
#pragma unroll
    for (int j = 0; j < 8; j++) {
        kA[j] = *(const float4*)&sK[lane * 36 + 4 * j];
        kB[j] = *(const float4*)&sK[(lane + 32) * 36 + 4 * j];
    }

    float s0v[7], s1v[7];
#pragma unroll
    for (int i = 0; i < 7; i++) {
        int p = warp + 8 * i;
        float s0 = 0.f, s1 = 0.f;
        if (p < 49) {
#pragma unroll
            for (int j = 0; j < 8; j++) {
                float4 qv = *(const float4*)&sQ[p * 36 + 4 * j];
                s0 = fmaf(qv.x, kA[j].x, s0); s0 = fmaf(qv.y, kA[j].y, s0);
                s0 = fmaf(qv.z, kA[j].z, s0); s0 = fmaf(qv.w, kA[j].w, s0);
                s1 = fmaf(qv.x, kB[j].x, s1); s1 = fmaf(qv.y, kB[j].y, s1);
                s1 = fmaf(qv.z, kB[j].z, s1); s1 = fmaf(qv.w, kB[j].w, s1);
            }
        }
        s0v[i] = s0 * scale;
        s1v[i] = s1 * scale;
    }

    float mx[7];
#pragma unroll
    for (int i = 0; i < 7; i++) mx[i] = hi ? fmaxf(s0v[i], s1v[i]) : s0v[i];
#pragma unroll
    for (int o = 16; o > 0; o >>= 1) {
#pragma unroll
        for (int i = 0; i < 7; i++)
            mx[i] = fmaxf(mx[i], __shfl_xor_sync(0xffffffffu, mx[i], o));
    }
    float e0a[7], e1a[7], sm[7];
#pragma unroll
    for (int i = 0; i < 7; i++) {
        e0a[i] = __expf(s0v[i] - mx[i]);
        e1a[i] = hi ? __expf(s1v[i] - mx[i]) : 0.f;
        sm[i] = e0a[i] + e1a[i];
    }
#pragma unroll
    for (int o = 16; o > 0; o >>= 1) {
#pragma unroll
        for (int i = 0; i < 7; i++)
            sm[i] += __shfl_xor_sync(0xffffffffu, sm[i], o);
    }
    float rinv[7];
#pragma unroll
    for (int i = 0; i < 7; i++) {
        rinv[i] = 1.f / sm[i];
        int p = warp + 8 * i;
        if (p < 49) {
            sP[p * 52 + lane] = e0a[i];
            if (lane < 17) sP[p * 52 + 32 + lane] = e1a[i];
        }
    }
    __syncthreads();

    float accv[7];
#pragma unroll
    for (int i = 0; i < 7; i++) accv[i] = 0.f;
#pragma unroll
    for (int j = 0; j < 13; j++) {
        float4 pv[7];
#pragma unroll
        for (int i = 0; i < 7; i++) {
            int p = warp + 8 * i;
            pv[i] = (p < 49) ? *(const float4*)&sP[p * 52 + 4 * j]
                             : make_float4(0.f, 0.f, 0.f, 0.f);
        }
        {
            float v0 = sV[(4 * j + 0) * 36 + lane];
#pragma unroll
            for (int i = 0; i < 7; i++) accv[i] = fmaf(pv[i].x, v0, accv[i]);
            float v1 = sV[(4 * j + 1) * 36 + lane];
#pragma unroll
            for (int i = 0; i < 7; i++) accv[i] = fmaf(pv[i].y, v1, accv[i]);
            float v2 = sV[(4 * j + 2) * 36 + lane];
#pragma unroll
            for (int i = 0; i < 7; i++) accv[i] = fmaf(pv[i].z, v2, accv[i]);
            float v3 = sV[(4 * j + 3) * 36 + lane];
#pragma unroll
            for (int i = 0; i < 7; i++) accv[i] = fmaf(pv[i].w, v3, accv[i]);
        }
    }

#pragma unroll
    for (int i = 0; i < 7; i++) {
        int p = warp + 8 * i;
        if (p < 49) {
            float val = accv[i] * rinv[i];
            __nv_bfloat16 h = __float2bfloat16(val);
            __nv_bfloat16 l = __float2bfloat16(val - __bfloat162float(h));
            int col = (headOff + hl) * 32 + lane;
            for (int t = 0; t < ntile; t++) {
                int nout = (t * nwin + rg) * 49 + p;
                size_t off = ((size_t)b * NTOK + nout) * 384 + col;
                g_Zh[off] = h;
                g_Zl[off] = l;
            }
        }
    }
}

// ---------------- launch ---------------------------------------------------------
extern "C" void kernel_launch(void* const* d_in, const int* in_sizes, int n_in,
                              void* d_out, int out_size)
{
    const float* x     = (const float*)d_in[0];
    const float* Wq    = (const float*)d_in[1];
    const float* Wkv   = (const float*)d_in[2];
    const float* Wproj = (const float*)d_in[3];
    const float* bproj = (const float*)d_in[4];
    const float* c1w   = (const float*)d_in[5];
    const float* c1b   = (const float*)d_in[6];
    const float* c2w   = (const float*)d_in[7];
    const float* c2b   = (const float*)d_in[8];
    float* out = (float*)d_out;

    cudaFuncSetAttribute(gemm_mma, cudaFuncAttributeMaxDynamicSharedMemorySize, SMEM_GEMM);

    split_x<<<4704, 256>>>((const float4*)x);
    make_wt_qkv<<<1728, 256>>>(Wq, Wkv);
    make_wt_proj<<<576, 256>>>(Wproj);
    gemm_mma<<<dim3(9, 784), 256, SMEM_GEMM>>>(nullptr, nullptr, 0);   // 4th -> ncu
    window_attn<<<32 * 4 * 64, 256>>>(0);
    dwconv_fused<<<dim3(128, 6), 256>>>(c1w, c1b, c2w, c2b);
    window_attn<<<32 * 4 * 16, 256>>>(1);
    window_attn<<<32 * 4 * 4,  256>>>(2);
    gemm_mma<<<dim3(3, 784), 256, SMEM_GEMM>>>(bproj, out, 1);
}